// round 1
// baseline (speedup 1.0000x reference)
#include <cuda_runtime.h>
#include <cuda_bf16.h>

// Problem constants (fixed by setup_inputs)
#define BROWS 8192
#define DDIM  2048
#define KCOLS 512
#define NPTS  17
#define DT    (2.0f / 17.0f)

// -------- scratch (device globals; no allocation allowed) --------
__device__ float g_norm2[KCOLS];                 // column squared norms of directions
__device__ float g_proj[BROWS * KCOLS];          // 16 MB projection matrix
__device__ float g_stat[2 * KCOLS];              // [0:512) sum, [512:1024) sumsq
__device__ float g_ab[2 * KCOLS];                // a = DT/(sd+1e-8), b = -DT*mu/(sd+1e-8)
__device__ float g_ecfR[NPTS * KCOLS];           // ECF real sums
__device__ float g_ecfI[NPTS * KCOLS];           // ECF imag sums

// -------- packed f32x2 helpers (sm_100+ FFMA2) --------
__device__ __forceinline__ unsigned long long ffma2(unsigned long long a,
                                                    unsigned long long b,
                                                    unsigned long long c) {
    unsigned long long d;
    asm("fma.rn.f32x2 %0, %1, %2, %3;" : "=l"(d) : "l"(a), "l"(b), "l"(c));
    return d;
}
__device__ __forceinline__ unsigned long long dup2(float a) {
    unsigned long long r;
    asm("mov.b64 %0, {%1, %1};" : "=l"(r) : "f"(a));
    return r;
}
__device__ __forceinline__ float2 unpack2(unsigned long long v) {
    float2 r;
    asm("mov.b64 {%0, %1}, %2;" : "=f"(r.x), "=f"(r.y) : "l"(v));
    return r;
}

// -------- K0: zero the atomic accumulators --------
__global__ void k_zero() {
    int i = blockIdx.x * blockDim.x + threadIdx.x;
    if (i < KCOLS) g_norm2[i] = 0.f;
    if (i < 2 * KCOLS) g_stat[i] = 0.f;
    if (i < NPTS * KCOLS) { g_ecfR[i] = 0.f; g_ecfI[i] = 0.f; }
}

// -------- K1: column squared norms of directions (D x K, row-major) --------
// grid 32 blocks x 256: colgroup = bx&1 (256 cols each), chunk = bx>>1 (16 chunks of 128 rows)
__global__ void k_norm2(const float* __restrict__ dir) {
    int k  = (blockIdx.x & 1) * 256 + threadIdx.x;
    int d0 = (blockIdx.x >> 1) * 128;
    float s = 0.f;
#pragma unroll 8
    for (int d = 0; d < 128; d++) {
        float v = dir[(d0 + d) * KCOLS + k];
        s = fmaf(v, v, s);
    }
    atomicAdd(&g_norm2[k], s);
}

// -------- K2: GEMM proj = A(8192x2048) @ (dir * rnorm)(2048x512) --------
// 128x128 block tile, BK=16, 256 threads, 8x8 per thread, packed f32x2 inner loop.
__global__ __launch_bounds__(256, 2) void k_gemm(const float* __restrict__ A,
                                                 const float* __restrict__ Bd) {
    __shared__ float As[16][132];   // transposed A tile (pad 4 words vs 2-way store conflict)
    __shared__ float Bs[16][128];

    const int tid = threadIdx.x;
    const int n0 = blockIdx.x * 128;
    const int m0 = blockIdx.y * 128;

    // A loads: row ar (and ar+64), 4-float chunk ac within the 16-wide K slab
    const int ar = tid >> 2;
    const int ac = tid & 3;
    // B loads: k-row bk (and bk+8), 4-float col chunk bc
    const int bk = tid >> 5;
    const int bc = tid & 31;

    float4 rn4;
    rn4.x = rsqrtf(fmaxf(g_norm2[n0 + bc * 4 + 0], 1e-24f));
    rn4.y = rsqrtf(fmaxf(g_norm2[n0 + bc * 4 + 1], 1e-24f));
    rn4.z = rsqrtf(fmaxf(g_norm2[n0 + bc * 4 + 2], 1e-24f));
    rn4.w = rsqrtf(fmaxf(g_norm2[n0 + bc * 4 + 3], 1e-24f));

    const float* Aptr = A + (m0 + ar) * DDIM + ac * 4;
    const float* Bptr = Bd + bk * KCOLS + n0 + bc * 4;

    // prologue loads (k0 = 0)
    float4 a0 = *(const float4*)(Aptr);
    float4 a1 = *(const float4*)(Aptr + 64 * DDIM);
    float4 b0 = *(const float4*)(Bptr);
    float4 b1 = *(const float4*)(Bptr + 8 * KCOLS);

    unsigned long long acc[8][4];
#pragma unroll
    for (int i = 0; i < 8; i++)
#pragma unroll
        for (int j = 0; j < 4; j++) acc[i][j] = 0ULL;

    const int tx = tid & 15;
    const int ty = tid >> 4;

    for (int k0 = 0; k0 < DDIM; k0 += 16) {
        __syncthreads();   // previous compute done reading smem
        As[ac * 4 + 0][ar]      = a0.x;
        As[ac * 4 + 1][ar]      = a0.y;
        As[ac * 4 + 2][ar]      = a0.z;
        As[ac * 4 + 3][ar]      = a0.w;
        As[ac * 4 + 0][ar + 64] = a1.x;
        As[ac * 4 + 1][ar + 64] = a1.y;
        As[ac * 4 + 2][ar + 64] = a1.z;
        As[ac * 4 + 3][ar + 64] = a1.w;
        float4 s0 = make_float4(b0.x * rn4.x, b0.y * rn4.y, b0.z * rn4.z, b0.w * rn4.w);
        float4 s1 = make_float4(b1.x * rn4.x, b1.y * rn4.y, b1.z * rn4.z, b1.w * rn4.w);
        *(float4*)&Bs[bk][bc * 4]     = s0;
        *(float4*)&Bs[bk + 8][bc * 4] = s1;
        __syncthreads();

        if (k0 + 16 < DDIM) {   // prefetch next slab; latency overlaps compute below
            a0 = *(const float4*)(Aptr + (k0 + 16));
            a1 = *(const float4*)(Aptr + (k0 + 16) + 64 * DDIM);
            b0 = *(const float4*)(Bptr + (k0 + 16) * KCOLS);
            b1 = *(const float4*)(Bptr + (k0 + 16) * KCOLS + 8 * KCOLS);
        }

#pragma unroll
        for (int kk = 0; kk < 16; kk++) {
            float4 av0 = *(const float4*)&As[kk][ty * 8];
            float4 av1 = *(const float4*)&As[kk][ty * 8 + 4];
            ulonglong2 bv0 = *(const ulonglong2*)&Bs[kk][tx * 8];
            ulonglong2 bv1 = *(const ulonglong2*)&Bs[kk][tx * 8 + 4];
            unsigned long long bb[4] = { bv0.x, bv0.y, bv1.x, bv1.y };
            float av[8] = { av0.x, av0.y, av0.z, av0.w, av1.x, av1.y, av1.z, av1.w };
#pragma unroll
            for (int i = 0; i < 8; i++) {
                unsigned long long ad = dup2(av[i]);
#pragma unroll
                for (int j = 0; j < 4; j++) acc[i][j] = ffma2(ad, bb[j], acc[i][j]);
            }
        }
    }

    // epilogue: unpack accumulators and store C tile
#pragma unroll
    for (int i = 0; i < 8; i++) {
        int row = m0 + ty * 8 + i;
        float2 c0 = unpack2(acc[i][0]);
        float2 c1 = unpack2(acc[i][1]);
        float2 c2 = unpack2(acc[i][2]);
        float2 c3 = unpack2(acc[i][3]);
        *(float4*)&g_proj[row * KCOLS + n0 + tx * 8]     = make_float4(c0.x, c0.y, c1.x, c1.y);
        *(float4*)&g_proj[row * KCOLS + n0 + tx * 8 + 4] = make_float4(c2.x, c2.y, c3.x, c3.y);
    }
}

// -------- K3: per-column sum / sumsq over proj --------
// grid 128 blocks x 256: colgroup = bx&1, chunk = bx>>1 (64 chunks of 128 rows)
__global__ void k_stats() {
    int k  = (blockIdx.x & 1) * 256 + threadIdx.x;
    int b0 = (blockIdx.x >> 1) * 128;
    float s = 0.f, s2 = 0.f;
#pragma unroll 8
    for (int r = 0; r < 128; r++) {
        float v = g_proj[(b0 + r) * KCOLS + k];
        s += v;
        s2 = fmaf(v, v, s2);
    }
    atomicAdd(&g_stat[k], s);
    atomicAdd(&g_stat[KCOLS + k], s2);
}

// -------- K4: a,b affine (folds standardization AND the dt angle scale) --------
__global__ void k_ab() {
    int k = blockIdx.x * blockDim.x + threadIdx.x;
    if (k >= KCOLS) return;
    float sum = g_stat[k];
    float sq  = g_stat[KCOLS + k];
    float mu  = sum * (1.0f / (float)BROWS);
    float var = (sq - (float)BROWS * mu * mu) * (1.0f / (float)(BROWS - 1));
    float sd  = sqrtf(fmaxf(var, 0.f));
    float a   = 1.0f / (sd + 1e-8f);
    g_ab[k]         = DT * a;
    g_ab[KCOLS + k] = DT * (-mu * a);
}

// -------- K5: ECF accumulation via angle-addition recurrence --------
// block = 8 warps; warp covers 32 consecutive k (coalesced), each warp a 128-row slice.
// grid (16 colgroups, 8 rowblocks) = 128 blocks.
__global__ __launch_bounds__(256) void k_ecf() {
    int lane = threadIdx.x & 31;
    int w    = threadIdx.x >> 5;
    int k    = blockIdx.x * 32 + lane;
    int b0   = blockIdx.y * 1024 + w * 128;

    float a = g_ab[k];
    float b = g_ab[KCOLS + k];

    float accR[NPTS], accI[NPTS];
#pragma unroll
    for (int j = 0; j < NPTS; j++) { accR[j] = 0.f; accI[j] = 0.f; }

#pragma unroll 2
    for (int r = 0; r < 128; r++) {
        float x = fmaf(a, g_proj[(b0 + r) * KCOLS + k], b);   // = dt * standardized proj
        float s1, c1;
        __sincosf(x, &s1, &c1);
        float c = c1, s = s1;
        accR[0] += c1;
        accI[0] += s1;
#pragma unroll
        for (int j = 1; j < NPTS; j++) {
            float cn = fmaf(c, c1, -s * s1);
            float sn = fmaf(s, c1,  c * s1);
            accR[j] += cn;
            accI[j] += sn;
            c = cn; s = sn;
        }
    }

#pragma unroll
    for (int j = 0; j < NPTS; j++) {
        atomicAdd(&g_ecfR[j * KCOLS + k], accR[j]);
        atomicAdd(&g_ecfI[j * KCOLS + k], accI[j]);
    }
}

// -------- K6: final scalar --------
__global__ void k_final(float* __restrict__ out) {
    __shared__ float sd[KCOLS];
    int k = threadIdx.x;
    float acc = 0.f;
#pragma unroll
    for (int j = 0; j < NPTS; j++) {
        float t   = (float)(j + 1) * DT;
        float er  = g_ecfR[j * KCOLS + k] * (1.0f / (float)BROWS);
        float ei  = g_ecfI[j * KCOLS + k] * (1.0f / (float)BROWS);
        float tcf = expf(-0.5f * t * t);
        float wq  = (j == 0 || j == NPTS - 1) ? (DT * 0.5f) : DT;
        float d   = er - tcf;                 // (er-tcf)^2 + ei^2: avoids cancellation
        acc = fmaf(wq, fmaf(d, d, ei * ei), acc);
    }
    sd[k] = acc;
    __syncthreads();
    for (int s = 256; s > 0; s >>= 1) {
        if (k < s) sd[k] += sd[k + s];
        __syncthreads();
    }
    if (k == 0) out[0] = sd[0] * (1.0f / (float)KCOLS);
}

extern "C" void kernel_launch(void* const* d_in, const int* in_sizes, int n_in,
                              void* d_out, int out_size) {
    const float* emb = (const float*)d_in[0];   // (8192, 2048)
    const float* dir = (const float*)d_in[1];   // (2048, 512)
    float* out = (float*)d_out;

    k_zero<<<(NPTS * KCOLS + 255) / 256, 256>>>();
    k_norm2<<<32, 256>>>(dir);
    k_gemm<<<dim3(KCOLS / 128, BROWS / 128), 256>>>(emb, dir);
    k_stats<<<128, 256>>>();
    k_ab<<<2, 256>>>();
    k_ecf<<<dim3(KCOLS / 32, 8), 256>>>();
    k_final<<<1, KCOLS>>>(out);
}

// round 2
// speedup vs baseline: 1.0023x; 1.0023x over previous
#include <cuda_runtime.h>
#include <cuda_bf16.h>

// Problem constants (fixed by setup_inputs)
#define BROWS 8192
#define DDIM  2048
#define KCOLS 512
#define NPTS  17
#define DT    (2.0f / 17.0f)

// -------- scratch (device globals; no allocation allowed) --------
__device__ float g_norm2[KCOLS];                 // column squared norms of directions
__device__ float g_proj[BROWS * KCOLS];          // 16 MB projection matrix
__device__ float g_stat[2 * KCOLS];              // [0:512) sum, [512:1024) sumsq
__device__ float g_ab[2 * KCOLS];                // a = DT/(sd+1e-8), b = -DT*mu/(sd+1e-8)
__device__ float g_ecfR[NPTS * KCOLS];           // ECF real sums
__device__ float g_ecfI[NPTS * KCOLS];           // ECF imag sums

// -------- packed f32x2 helpers (sm_100+ FFMA2) --------
__device__ __forceinline__ unsigned long long ffma2(unsigned long long a,
                                                    unsigned long long b,
                                                    unsigned long long c) {
    unsigned long long d;
    asm("fma.rn.f32x2 %0, %1, %2, %3;" : "=l"(d) : "l"(a), "l"(b), "l"(c));
    return d;
}
__device__ __forceinline__ unsigned long long dup2(float a) {
    unsigned long long r;
    asm("mov.b64 %0, {%1, %1};" : "=l"(r) : "f"(a));
    return r;
}
__device__ __forceinline__ float2 unpack2(unsigned long long v) {
    float2 r;
    asm("mov.b64 {%0, %1}, %2;" : "=f"(r.x), "=f"(r.y) : "l"(v));
    return r;
}

// -------- K0: zero the atomic accumulators --------
__global__ void k_zero() {
    int i = blockIdx.x * blockDim.x + threadIdx.x;
    if (i < KCOLS) g_norm2[i] = 0.f;
    if (i < 2 * KCOLS) g_stat[i] = 0.f;
    if (i < NPTS * KCOLS) { g_ecfR[i] = 0.f; g_ecfI[i] = 0.f; }
}

// -------- K1: column squared norms of directions (D x K, row-major) --------
// grid 32 blocks x 256: colgroup = bx&1 (256 cols each), chunk = bx>>1 (16 chunks of 128 rows)
__global__ void k_norm2(const float* __restrict__ dir) {
    int k  = (blockIdx.x & 1) * 256 + threadIdx.x;
    int d0 = (blockIdx.x >> 1) * 128;
    float s = 0.f;
#pragma unroll 8
    for (int d = 0; d < 128; d++) {
        float v = dir[(d0 + d) * KCOLS + k];
        s = fmaf(v, v, s);
    }
    atomicAdd(&g_norm2[k], s);
}

// -------- K2: GEMM proj = A(8192x2048) @ (dir * rnorm)(2048x512) --------
// 128x128 block tile, BK=16, 256 threads, 8x8 per thread, packed f32x2 inner loop.
__global__ __launch_bounds__(256, 2) void k_gemm(const float* __restrict__ A,
                                                 const float* __restrict__ Bd) {
    __shared__ float As[16][132];   // transposed A tile (pad 4 words vs 2-way store conflict)
    __shared__ float Bs[16][128];

    const int tid = threadIdx.x;
    const int n0 = blockIdx.x * 128;
    const int m0 = blockIdx.y * 128;

    // A loads: row ar (and ar+64), 4-float chunk ac within the 16-wide K slab
    const int ar = tid >> 2;
    const int ac = tid & 3;
    // B loads: k-row bk (and bk+8), 4-float col chunk bc
    const int bk = tid >> 5;
    const int bc = tid & 31;

    float4 rn4;
    rn4.x = rsqrtf(fmaxf(g_norm2[n0 + bc * 4 + 0], 1e-24f));
    rn4.y = rsqrtf(fmaxf(g_norm2[n0 + bc * 4 + 1], 1e-24f));
    rn4.z = rsqrtf(fmaxf(g_norm2[n0 + bc * 4 + 2], 1e-24f));
    rn4.w = rsqrtf(fmaxf(g_norm2[n0 + bc * 4 + 3], 1e-24f));

    const float* Aptr = A + (m0 + ar) * DDIM + ac * 4;
    const float* Bptr = Bd + bk * KCOLS + n0 + bc * 4;

    // prologue loads (k0 = 0)
    float4 a0 = *(const float4*)(Aptr);
    float4 a1 = *(const float4*)(Aptr + 64 * DDIM);
    float4 b0 = *(const float4*)(Bptr);
    float4 b1 = *(const float4*)(Bptr + 8 * KCOLS);

    unsigned long long acc[8][4];
#pragma unroll
    for (int i = 0; i < 8; i++)
#pragma unroll
        for (int j = 0; j < 4; j++) acc[i][j] = 0ULL;

    const int tx = tid & 15;
    const int ty = tid >> 4;

    for (int k0 = 0; k0 < DDIM; k0 += 16) {
        __syncthreads();   // previous compute done reading smem
        As[ac * 4 + 0][ar]      = a0.x;
        As[ac * 4 + 1][ar]      = a0.y;
        As[ac * 4 + 2][ar]      = a0.z;
        As[ac * 4 + 3][ar]      = a0.w;
        As[ac * 4 + 0][ar + 64] = a1.x;
        As[ac * 4 + 1][ar + 64] = a1.y;
        As[ac * 4 + 2][ar + 64] = a1.z;
        As[ac * 4 + 3][ar + 64] = a1.w;
        float4 s0 = make_float4(b0.x * rn4.x, b0.y * rn4.y, b0.z * rn4.z, b0.w * rn4.w);
        float4 s1 = make_float4(b1.x * rn4.x, b1.y * rn4.y, b1.z * rn4.z, b1.w * rn4.w);
        *(float4*)&Bs[bk][bc * 4]     = s0;
        *(float4*)&Bs[bk + 8][bc * 4] = s1;
        __syncthreads();

        if (k0 + 16 < DDIM) {   // prefetch next slab; latency overlaps compute below
            a0 = *(const float4*)(Aptr + (k0 + 16));
            a1 = *(const float4*)(Aptr + (k0 + 16) + 64 * DDIM);
            b0 = *(const float4*)(Bptr + (k0 + 16) * KCOLS);
            b1 = *(const float4*)(Bptr + (k0 + 16) * KCOLS + 8 * KCOLS);
        }

#pragma unroll
        for (int kk = 0; kk < 16; kk++) {
            float4 av0 = *(const float4*)&As[kk][ty * 8];
            float4 av1 = *(const float4*)&As[kk][ty * 8 + 4];
            ulonglong2 bv0 = *(const ulonglong2*)&Bs[kk][tx * 8];
            ulonglong2 bv1 = *(const ulonglong2*)&Bs[kk][tx * 8 + 4];
            unsigned long long bb[4] = { bv0.x, bv0.y, bv1.x, bv1.y };
            float av[8] = { av0.x, av0.y, av0.z, av0.w, av1.x, av1.y, av1.z, av1.w };
#pragma unroll
            for (int i = 0; i < 8; i++) {
                unsigned long long ad = dup2(av[i]);
#pragma unroll
                for (int j = 0; j < 4; j++) acc[i][j] = ffma2(ad, bb[j], acc[i][j]);
            }
        }
    }

    // epilogue: unpack accumulators and store C tile
#pragma unroll
    for (int i = 0; i < 8; i++) {
        int row = m0 + ty * 8 + i;
        float2 c0 = unpack2(acc[i][0]);
        float2 c1 = unpack2(acc[i][1]);
        float2 c2 = unpack2(acc[i][2]);
        float2 c3 = unpack2(acc[i][3]);
        *(float4*)&g_proj[row * KCOLS + n0 + tx * 8]     = make_float4(c0.x, c0.y, c1.x, c1.y);
        *(float4*)&g_proj[row * KCOLS + n0 + tx * 8 + 4] = make_float4(c2.x, c2.y, c3.x, c3.y);
    }
}

// -------- K3: per-column sum / sumsq over proj --------
// grid 128 blocks x 256: colgroup = bx&1, chunk = bx>>1 (64 chunks of 128 rows)
__global__ void k_stats() {
    int k  = (blockIdx.x & 1) * 256 + threadIdx.x;
    int b0 = (blockIdx.x >> 1) * 128;
    float s = 0.f, s2 = 0.f;
#pragma unroll 8
    for (int r = 0; r < 128; r++) {
        float v = g_proj[(b0 + r) * KCOLS + k];
        s += v;
        s2 = fmaf(v, v, s2);
    }
    atomicAdd(&g_stat[k], s);
    atomicAdd(&g_stat[KCOLS + k], s2);
}

// -------- K4: a,b affine (folds standardization AND the dt angle scale) --------
__global__ void k_ab() {
    int k = blockIdx.x * blockDim.x + threadIdx.x;
    if (k >= KCOLS) return;
    float sum = g_stat[k];
    float sq  = g_stat[KCOLS + k];
    float mu  = sum * (1.0f / (float)BROWS);
    float var = (sq - (float)BROWS * mu * mu) * (1.0f / (float)(BROWS - 1));
    float sd  = sqrtf(fmaxf(var, 0.f));
    float a   = 1.0f / (sd + 1e-8f);
    g_ab[k]         = DT * a;
    g_ab[KCOLS + k] = DT * (-mu * a);
}

// -------- K5: ECF accumulation via angle-addition recurrence --------
// block = 8 warps; warp covers 32 consecutive k (coalesced), each warp a 128-row slice.
// grid (16 colgroups, 8 rowblocks) = 128 blocks.
__global__ __launch_bounds__(256) void k_ecf() {
    int lane = threadIdx.x & 31;
    int w    = threadIdx.x >> 5;
    int k    = blockIdx.x * 32 + lane;
    int b0   = blockIdx.y * 1024 + w * 128;

    float a = g_ab[k];
    float b = g_ab[KCOLS + k];

    float accR[NPTS], accI[NPTS];
#pragma unroll
    for (int j = 0; j < NPTS; j++) { accR[j] = 0.f; accI[j] = 0.f; }

#pragma unroll 2
    for (int r = 0; r < 128; r++) {
        float x = fmaf(a, g_proj[(b0 + r) * KCOLS + k], b);   // = dt * standardized proj
        float s1, c1;
        __sincosf(x, &s1, &c1);
        float c = c1, s = s1;
        accR[0] += c1;
        accI[0] += s1;
#pragma unroll
        for (int j = 1; j < NPTS; j++) {
            float cn = fmaf(c, c1, -s * s1);
            float sn = fmaf(s, c1,  c * s1);
            accR[j] += cn;
            accI[j] += sn;
            c = cn; s = sn;
        }
    }

#pragma unroll
    for (int j = 0; j < NPTS; j++) {
        atomicAdd(&g_ecfR[j * KCOLS + k], accR[j]);
        atomicAdd(&g_ecfI[j * KCOLS + k], accI[j]);
    }
}

// -------- K6: final scalar --------
__global__ void k_final(float* __restrict__ out) {
    __shared__ float sd[KCOLS];
    int k = threadIdx.x;
    float acc = 0.f;
#pragma unroll
    for (int j = 0; j < NPTS; j++) {
        float t   = (float)(j + 1) * DT;
        float er  = g_ecfR[j * KCOLS + k] * (1.0f / (float)BROWS);
        float ei  = g_ecfI[j * KCOLS + k] * (1.0f / (float)BROWS);
        float tcf = expf(-0.5f * t * t);
        float wq  = (j == 0 || j == NPTS - 1) ? (DT * 0.5f) : DT;
        float d   = er - tcf;                 // (er-tcf)^2 + ei^2: avoids cancellation
        acc = fmaf(wq, fmaf(d, d, ei * ei), acc);
    }
    sd[k] = acc;
    __syncthreads();
    for (int s = 256; s > 0; s >>= 1) {
        if (k < s) sd[k] += sd[k + s];
        __syncthreads();
    }
    if (k == 0) out[0] = sd[0] * (1.0f / (float)KCOLS);
}

extern "C" void kernel_launch(void* const* d_in, const int* in_sizes, int n_in,
                              void* d_out, int out_size) {
    const float* emb = (const float*)d_in[0];   // (8192, 2048)
    const float* dir = (const float*)d_in[1];   // (2048, 512)
    float* out = (float*)d_out;

    k_zero<<<(NPTS * KCOLS + 255) / 256, 256>>>();
    k_norm2<<<32, 256>>>(dir);
    k_gemm<<<dim3(KCOLS / 128, BROWS / 128), 256>>>(emb, dir);
    k_stats<<<128, 256>>>();
    k_ab<<<2, 256>>>();
    k_ecf<<<dim3(KCOLS / 32, 8), 256>>>();
    k_final<<<1, KCOLS>>>(out);
}

// round 4
// speedup vs baseline: 1.9548x; 1.9503x over previous
#include <cuda_runtime.h>
#include <cuda_bf16.h>
#include <cstdint>

#define BROWS 8192
#define DDIM  2048
#define KCOLS 512
#define NPTS  17
#define DT    (2.0f / 17.0f)

// ---- GEMM tiling ----
#define BM 128
#define BN 128
#define BK 32
#define KITER (DDIM / BK)          // 64
#define TSTRIDE 40                 // bf16 halves per smem row (32 data + 8 pad)
#define TILEB (128 * TSTRIDE * 2)  // 10240 bytes per tile
#define OAH 0
#define OAL (1 * TILEB)
#define OBH (2 * TILEB)
#define OBL (3 * TILEB)
#define STAGEB (4 * TILEB)         // 40960 bytes per stage
#define GEMM_SMEM (2 * STAGEB)     // 81920

// ---- device scratch ----
__device__ float g_norm2[KCOLS];
__device__ __nv_bfloat16 g_A_hi[(size_t)BROWS * DDIM];
__device__ __nv_bfloat16 g_A_lo[(size_t)BROWS * DDIM];
__device__ __nv_bfloat16 g_Bt_hi[KCOLS * DDIM];   // [n][k] normalized, hi
__device__ __nv_bfloat16 g_Bt_lo[KCOLS * DDIM];   // [n][k] residual, lo
__device__ float g_proj[(size_t)BROWS * KCOLS];
__device__ float g_stat[2 * KCOLS];
__device__ float g_ab[2 * KCOLS];
__device__ float g_ecfR[NPTS * KCOLS];
__device__ float g_ecfI[NPTS * KCOLS];

// ---- helpers ----
__device__ __forceinline__ uint32_t smem_u32(const void* p) {
    uint32_t a;
    asm("{ .reg .u64 t; cvta.to.shared.u64 t, %1; cvt.u32.u64 %0, t; }" : "=r"(a) : "l"(p));
    return a;
}
__device__ __forceinline__ void cp16(uint32_t dst, const void* src) {
    asm volatile("cp.async.cg.shared.global [%0], [%1], 16;" :: "r"(dst), "l"(src));
}
#define CP_COMMIT() asm volatile("cp.async.commit_group;" ::: "memory")
#define CP_WAIT1()  asm volatile("cp.async.wait_group 1;" ::: "memory")

__device__ __forceinline__ void ldsm4(uint32_t* r, uint32_t addr) {
    asm volatile("ldmatrix.sync.aligned.m8n8.x4.shared.b16 {%0,%1,%2,%3}, [%4];"
                 : "=r"(r[0]), "=r"(r[1]), "=r"(r[2]), "=r"(r[3]) : "r"(addr));
}
__device__ __forceinline__ void ldsm2(uint32_t* r, uint32_t addr) {
    asm volatile("ldmatrix.sync.aligned.m8n8.x2.shared.b16 {%0,%1}, [%2];"
                 : "=r"(r[0]), "=r"(r[1]) : "r"(addr));
}
__device__ __forceinline__ void mma16816(float* d, const uint32_t* a, const uint32_t* b) {
    asm volatile("mma.sync.aligned.m16n8k16.row.col.f32.bf16.bf16.f32 "
                 "{%0,%1,%2,%3}, {%4,%5,%6,%7}, {%8,%9}, {%0,%1,%2,%3};"
                 : "+f"(d[0]), "+f"(d[1]), "+f"(d[2]), "+f"(d[3])
                 : "r"(a[0]), "r"(a[1]), "r"(a[2]), "r"(a[3]), "r"(b[0]), "r"(b[1]));
}

typedef unsigned long long ull;
__device__ __forceinline__ ull ffma2(ull a, ull b, ull c) {
    ull d; asm("fma.rn.f32x2 %0, %1, %2, %3;" : "=l"(d) : "l"(a), "l"(b), "l"(c)); return d;
}
__device__ __forceinline__ ull mul2(ull a, ull b) {
    ull d; asm("mul.rn.f32x2 %0, %1, %2;" : "=l"(d) : "l"(a), "l"(b)); return d;
}
__device__ __forceinline__ ull add2(ull a, ull b) {
    ull d; asm("add.rn.f32x2 %0, %1, %2;" : "=l"(d) : "l"(a), "l"(b)); return d;
}
__device__ __forceinline__ ull dup2(float a) {
    ull r; asm("mov.b64 %0, {%1, %1};" : "=l"(r) : "f"(a)); return r;
}
__device__ __forceinline__ ull pack2(float lo, float hi) {
    ull r; asm("mov.b64 %0, {%1, %2};" : "=l"(r) : "f"(lo), "f"(hi)); return r;
}
__device__ __forceinline__ float2 unpack2(ull v) {
    float2 r; asm("mov.b64 {%0, %1}, %2;" : "=f"(r.x), "=f"(r.y) : "l"(v)); return r;
}
__device__ __forceinline__ ull neg2(ull v) { return v ^ 0x8000000080000000ULL; }

// -------- K0: zero accumulators --------
__global__ void k_zero() {
    int i = blockIdx.x * blockDim.x + threadIdx.x;
    if (i < KCOLS) g_norm2[i] = 0.f;
    if (i < 2 * KCOLS) g_stat[i] = 0.f;
    if (i < NPTS * KCOLS) { g_ecfR[i] = 0.f; g_ecfI[i] = 0.f; }
}

// -------- K1: column squared norms of directions --------
__global__ void k_norm2(const float* __restrict__ dir) {
    int k  = (blockIdx.x & 1) * 256 + threadIdx.x;
    int d0 = (blockIdx.x >> 1) * 32;
    float s = 0.f;
#pragma unroll 8
    for (int d = 0; d < 32; d++) {
        float v = dir[(size_t)(d0 + d) * KCOLS + k];
        s = fmaf(v, v, s);
    }
    atomicAdd(&g_norm2[k], s);
}

// -------- K2: normalize + transpose + bf16 hi/lo split of directions --------
__global__ void __launch_bounds__(256) k_prepB(const float* __restrict__ dir) {
    __shared__ float s[64][65];
    int t = threadIdx.x;
    int n0t = blockIdx.x * 64;
    int d0  = blockIdx.y * 64;
#pragma unroll
    for (int jj = 0; jj < 4; jj++) {
        int flat = jj * 256 + t;
        int d = flat >> 4;
        int nq = flat & 15;
        float4 v = *(const float4*)(dir + (size_t)(d0 + d) * KCOLS + n0t + nq * 4);
        s[d][nq * 4 + 0] = v.x; s[d][nq * 4 + 1] = v.y;
        s[d][nq * 4 + 2] = v.z; s[d][nq * 4 + 3] = v.w;
    }
    __syncthreads();
#pragma unroll
    for (int jj = 0; jj < 4; jj++) {
        int flat = jj * 256 + t;
        int n = flat >> 4;
        int dq = flat & 15;
        float rn = rsqrtf(fmaxf(g_norm2[n0t + n], 1e-24f));
        float x0 = s[dq * 4 + 0][n] * rn, x1 = s[dq * 4 + 1][n] * rn;
        float x2 = s[dq * 4 + 2][n] * rn, x3 = s[dq * 4 + 3][n] * rn;
        __nv_bfloat162 h01 = __floats2bfloat162_rn(x0, x1);
        __nv_bfloat162 h23 = __floats2bfloat162_rn(x2, x3);
        float l0 = x0 - __bfloat162float(h01.x), l1 = x1 - __bfloat162float(h01.y);
        float l2 = x2 - __bfloat162float(h23.x), l3 = x3 - __bfloat162float(h23.y);
        __nv_bfloat162 q01 = __floats2bfloat162_rn(l0, l1);
        __nv_bfloat162 q23 = __floats2bfloat162_rn(l2, l3);
        size_t o = (size_t)(n0t + n) * DDIM + d0 + dq * 4;
        *(uint2*)(g_Bt_hi + o) = make_uint2(*(uint32_t*)&h01, *(uint32_t*)&h23);
        *(uint2*)(g_Bt_lo + o) = make_uint2(*(uint32_t*)&q01, *(uint32_t*)&q23);
    }
}

// -------- K3: split A into bf16 hi/lo --------
__global__ void __launch_bounds__(256) k_prepA(const float* __restrict__ A) {
    size_t idx = ((size_t)blockIdx.x * 256 + threadIdx.x) * 4;
    float4 v = *(const float4*)(A + idx);
    __nv_bfloat162 h01 = __floats2bfloat162_rn(v.x, v.y);
    __nv_bfloat162 h23 = __floats2bfloat162_rn(v.z, v.w);
    float l0 = v.x - __bfloat162float(h01.x), l1 = v.y - __bfloat162float(h01.y);
    float l2 = v.z - __bfloat162float(h23.x), l3 = v.w - __bfloat162float(h23.y);
    __nv_bfloat162 q01 = __floats2bfloat162_rn(l0, l1);
    __nv_bfloat162 q23 = __floats2bfloat162_rn(l2, l3);
    *(uint2*)(g_A_hi + idx) = make_uint2(*(uint32_t*)&h01, *(uint32_t*)&h23);
    *(uint2*)(g_A_lo + idx) = make_uint2(*(uint32_t*)&q01, *(uint32_t*)&q23);
}

// -------- K4: HMMA split-bf16 GEMM with fused column stats --------
__global__ void __launch_bounds__(256, 2) k_gemm(void) {
    extern __shared__ char smem[];
    const uint32_t sbase = smem_u32(smem);
    const int tid  = threadIdx.x;
    const int lane = tid & 31;
    const int wid  = tid >> 5;
    const int wm   = wid >> 2;       // 0..1  (64-row strip)
    const int wn   = wid & 3;        // 0..3  (32-col strip)
    const int n0 = blockIdx.x * BN;
    const int m0 = blockIdx.y * BM;

    // ---- loader mapping: row = tid>>1, two 16B chunks at (tid&1)*32 ----
    const int lrow = tid >> 1;
    const int lcb  = (tid & 1) * 32;                     // byte offset in smem row
    const int lke  = (tid & 1) * 16;                     // element offset in gmem row
    const size_t aoff = (size_t)(m0 + lrow) * DDIM + lke;
    const size_t boff = (size_t)(n0 + lrow) * DDIM + lke;
    const uint32_t ldst = lrow * (TSTRIDE * 2) + lcb;

#define ISSUE(stg, ks) do {                                                   \
    uint32_t _d = sbase + (stg) * STAGEB + ldst;                              \
    size_t _k = (size_t)(ks) * BK;                                            \
    cp16(_d + OAH,      g_A_hi  + aoff + _k);                                 \
    cp16(_d + OAH + 16, g_A_hi  + aoff + _k + 8);                             \
    cp16(_d + OAL,      g_A_lo  + aoff + _k);                                 \
    cp16(_d + OAL + 16, g_A_lo  + aoff + _k + 8);                             \
    cp16(_d + OBH,      g_Bt_hi + boff + _k);                                 \
    cp16(_d + OBH + 16, g_Bt_hi + boff + _k + 8);                             \
    cp16(_d + OBL,      g_Bt_lo + boff + _k);                                 \
    cp16(_d + OBL + 16, g_Bt_lo + boff + _k + 8);                             \
} while (0)

    float acc[4][4][4];
#pragma unroll
    for (int i = 0; i < 4; i++)
#pragma unroll
        for (int j = 0; j < 4; j++)
#pragma unroll
            for (int q = 0; q < 4; q++) acc[i][j][q] = 0.f;

    // ldmatrix lane-address components (bytes)
    const uint32_t aRowB = (wm * 64 + (lane & 15)) * (TSTRIDE * 2) + ((lane >> 4) & 1) * 16;
    const uint32_t bRowB = (wn * 32 + (lane & 7))  * (TSTRIDE * 2) + ((lane >> 3) & 1) * 16;

    ISSUE(0, 0); CP_COMMIT();
    ISSUE(1, 1); CP_COMMIT();

    for (int i = 0; i < KITER; i++) {
        CP_WAIT1();
        __syncthreads();
        const uint32_t sb = sbase + (i & 1) * STAGEB;
#pragma unroll
        for (int k16 = 0; k16 < 2; k16++) {
            const uint32_t kb = k16 * 32;
            uint32_t af[4][4], bh[4][2], bl[4][2];
#pragma unroll
            for (int mf = 0; mf < 4; mf++)
                ldsm4(af[mf], sb + OAH + aRowB + mf * 16 * (TSTRIDE * 2) + kb);
#pragma unroll
            for (int nf = 0; nf < 4; nf++) {
                ldsm2(bh[nf], sb + OBH + bRowB + nf * 8 * (TSTRIDE * 2) + kb);
                ldsm2(bl[nf], sb + OBL + bRowB + nf * 8 * (TSTRIDE * 2) + kb);
            }
#pragma unroll
            for (int mf = 0; mf < 4; mf++)
#pragma unroll
                for (int nf = 0; nf < 4; nf++) {
                    mma16816(acc[mf][nf], af[mf], bh[nf]);
                    mma16816(acc[mf][nf], af[mf], bl[nf]);
                }
#pragma unroll
            for (int mf = 0; mf < 4; mf++)
                ldsm4(af[mf], sb + OAL + aRowB + mf * 16 * (TSTRIDE * 2) + kb);
#pragma unroll
            for (int mf = 0; mf < 4; mf++)
#pragma unroll
                for (int nf = 0; nf < 4; nf++)
                    mma16816(acc[mf][nf], af[mf], bh[nf]);
        }
        __syncthreads();
        if (i + 2 < KITER) ISSUE(i & 1, i + 2);
        CP_COMMIT();
    }

    // ---- epilogue: store proj + fused column stats ----
    float sc[8], sq[8];
#pragma unroll
    for (int e = 0; e < 8; e++) { sc[e] = 0.f; sq[e] = 0.f; }

#pragma unroll
    for (int mf = 0; mf < 4; mf++) {
        const int m = m0 + wm * 64 + mf * 16 + (lane >> 2);
#pragma unroll
        for (int nf = 0; nf < 4; nf++) {
            const int n = n0 + wn * 32 + nf * 8 + (lane & 3) * 2;
            float* c = acc[mf][nf];
            *(float2*)&g_proj[(size_t)m * KCOLS + n]       = make_float2(c[0], c[1]);
            *(float2*)&g_proj[(size_t)(m + 8) * KCOLS + n] = make_float2(c[2], c[3]);
            sc[nf * 2 + 0] += c[0] + c[2];
            sc[nf * 2 + 1] += c[1] + c[3];
            sq[nf * 2 + 0] += c[0] * c[0] + c[2] * c[2];
            sq[nf * 2 + 1] += c[1] * c[1] + c[3] * c[3];
        }
    }
#pragma unroll
    for (int off = 16; off >= 4; off >>= 1)
#pragma unroll
        for (int e = 0; e < 8; e++) {
            sc[e] += __shfl_down_sync(0xFFFFFFFF, sc[e], off);
            sq[e] += __shfl_down_sync(0xFFFFFFFF, sq[e], off);
        }
    if (lane < 4) {
#pragma unroll
        for (int nf = 0; nf < 4; nf++)
#pragma unroll
            for (int p = 0; p < 2; p++) {
                int col = n0 + wn * 32 + nf * 8 + 2 * lane + p;
                atomicAdd(&g_stat[col],         sc[nf * 2 + p]);
                atomicAdd(&g_stat[KCOLS + col], sq[nf * 2 + p]);
            }
    }
}

// -------- K5: a,b affine --------
__global__ void k_ab() {
    int k = blockIdx.x * blockDim.x + threadIdx.x;
    if (k >= KCOLS) return;
    float sum = g_stat[k];
    float sq  = g_stat[KCOLS + k];
    float mu  = sum * (1.0f / (float)BROWS);
    float var = (sq - (float)BROWS * mu * mu) * (1.0f / (float)(BROWS - 1));
    float sd  = sqrtf(fmaxf(var, 0.f));
    float a   = 1.0f / (sd + 1e-8f);
    g_ab[k]         = DT * a;
    g_ab[KCOLS + k] = DT * (-mu * a);
}

// -------- K6: ECF via packed-f32x2 Taylor sin/cos + angle recurrence --------
__global__ void __launch_bounds__(256) k_ecf() {
    __shared__ float part[8][2 * NPTS][32];
    const int lane = threadIdx.x & 31;
    const int w    = threadIdx.x >> 5;
    const int k    = blockIdx.x * 32 + lane;
    const int b0   = blockIdx.y * 512 + w * 64;

    const float a = g_ab[k];
    const float b = g_ab[KCOLS + k];

    const ull ONE = dup2(1.0f);
    const ull S1 = dup2(-1.6666667e-1f), S2 = dup2(8.3333333e-3f), S3 = dup2(-1.9841270e-4f);
    const ull C1 = dup2(-0.5f), C2 = dup2(4.1666668e-2f), C3 = dup2(-1.3888889e-3f), C4 = dup2(2.4801587e-5f);

    ull accR[NPTS], accI[NPTS];
#pragma unroll
    for (int j = 0; j < NPTS; j++) { accR[j] = 0ULL; accI[j] = 0ULL; }

#pragma unroll 2
    for (int r = 0; r < 32; r++) {
        float pA = g_proj[(size_t)(b0 + r) * KCOLS + k];
        float pB = g_proj[(size_t)(b0 + r + 32) * KCOLS + k];
        ull x  = pack2(fmaf(a, pA, b), fmaf(a, pB, b));
        ull x2 = mul2(x, x);
        ull ps = ffma2(x2, S3, S2); ps = ffma2(x2, ps, S1); ps = ffma2(x2, ps, ONE);
        ull s1 = mul2(x, ps);
        ull pc = ffma2(x2, C4, C3); pc = ffma2(x2, pc, C2); pc = ffma2(x2, pc, C1);
        ull c1 = ffma2(x2, pc, ONE);
        ull ns1 = neg2(s1);
        ull c = c1, s = s1;
        accR[0] = add2(accR[0], c1);
        accI[0] = add2(accI[0], s1);
#pragma unroll
        for (int j = 1; j < NPTS; j++) {
            ull cn = ffma2(s, ns1, mul2(c, c1));
            ull sn = ffma2(c, s1,  mul2(s, c1));
            accR[j] = add2(accR[j], cn);
            accI[j] = add2(accI[j], sn);
            c = cn; s = sn;
        }
    }
#pragma unroll
    for (int j = 0; j < NPTS; j++) {
        float2 fr = unpack2(accR[j]);
        float2 fi = unpack2(accI[j]);
        part[w][j][lane]        = fr.x + fr.y;
        part[w][NPTS + j][lane] = fi.x + fi.y;
    }
    __syncthreads();
    for (int e = threadIdx.x; e < 2 * NPTS * 32; e += 256) {
        int jj = e >> 5;
        int ln = e & 31;
        float s = 0.f;
#pragma unroll
        for (int ww = 0; ww < 8; ww++) s += part[ww][jj][ln];
        int kk = blockIdx.x * 32 + ln;
        if (jj < NPTS) atomicAdd(&g_ecfR[jj * KCOLS + kk], s);
        else           atomicAdd(&g_ecfI[(jj - NPTS) * KCOLS + kk], s);
    }
}

// -------- K7: final scalar --------
__global__ void k_final(float* __restrict__ out) {
    __shared__ float sd[KCOLS];
    int k = threadIdx.x;
    float acc = 0.f;
#pragma unroll
    for (int j = 0; j < NPTS; j++) {
        float t   = (float)(j + 1) * DT;
        float er  = g_ecfR[j * KCOLS + k] * (1.0f / (float)BROWS);
        float ei  = g_ecfI[j * KCOLS + k] * (1.0f / (float)BROWS);
        float tcf = expf(-0.5f * t * t);
        float wq  = (j == 0 || j == NPTS - 1) ? (DT * 0.5f) : DT;
        float d   = er - tcf;
        acc = fmaf(wq, fmaf(d, d, ei * ei), acc);
    }
    sd[k] = acc;
    __syncthreads();
    for (int s = 256; s > 0; s >>= 1) {
        if (k < s) sd[k] += sd[k + s];
        __syncthreads();
    }
    if (k == 0) out[0] = sd[0] * (1.0f / (float)KCOLS);
}

extern "C" void kernel_launch(void* const* d_in, const int* in_sizes, int n_in,
                              void* d_out, int out_size) {
    const float* emb = (const float*)d_in[0];   // (8192, 2048)
    const float* dir = (const float*)d_in[1];   // (2048, 512)
    float* out = (float*)d_out;

    cudaFuncSetAttribute(k_gemm, cudaFuncAttributeMaxDynamicSharedMemorySize, GEMM_SMEM);

    k_zero<<<(NPTS * KCOLS + 255) / 256, 256>>>();
    k_norm2<<<128, 256>>>(dir);
    k_prepB<<<dim3(KCOLS / 64, DDIM / 64), 256>>>(dir);
    k_prepA<<<(BROWS * DDIM) / (256 * 4), 256>>>(emb);
    k_gemm<<<dim3(KCOLS / BN, BROWS / BM), 256, GEMM_SMEM>>>();
    k_ab<<<2, 256>>>();
    k_ecf<<<dim3(KCOLS / 32, BROWS / 512), 256>>>();
    k_final<<<1, KCOLS>>>(out);
}

// round 5
// speedup vs baseline: 2.0082x; 1.0273x over previous
#include <cuda_runtime.h>
#include <cuda_bf16.h>
#include <cstdint>

#define BROWS 8192
#define DDIM  2048
#define KCOLS 512
#define NPTS  17
#define DT    (2.0f / 17.0f)

// ---- GEMM tiling ----
#define BM 128
#define BN 128
#define BK 32
#define KITER (DDIM / BK)          // 64
#define TSTRIDE 40                 // bf16 halves per smem row (32 data + 8 pad)
#define TILEB (128 * TSTRIDE * 2)  // 10240 bytes per tile
#define OAH 0
#define OAL (1 * TILEB)
#define OBH (2 * TILEB)
#define OBL (3 * TILEB)
#define STAGEB (4 * TILEB)         // 40960 bytes per stage
#define GEMM_SMEM (2 * STAGEB)     // 81920

// ---- device scratch ----
__device__ float g_norm2[KCOLS];
__device__ __nv_bfloat16 g_A_hi[(size_t)BROWS * DDIM];
__device__ __nv_bfloat16 g_A_lo[(size_t)BROWS * DDIM];
__device__ __nv_bfloat16 g_Bt_hi[KCOLS * DDIM];   // [n][k] normalized, hi
__device__ __nv_bfloat16 g_Bt_lo[KCOLS * DDIM];   // [n][k] residual, lo
__device__ float g_proj[(size_t)BROWS * KCOLS];
__device__ float g_stat[2 * KCOLS];
__device__ float g_ab[2 * KCOLS];
__device__ float g_ecfR[NPTS * KCOLS];
__device__ float g_ecfI[NPTS * KCOLS];

// ---- helpers ----
__device__ __forceinline__ uint32_t smem_u32(const void* p) {
    uint32_t a;
    asm("{ .reg .u64 t; cvta.to.shared.u64 t, %1; cvt.u32.u64 %0, t; }" : "=r"(a) : "l"(p));
    return a;
}
__device__ __forceinline__ void cp16(uint32_t dst, const void* src) {
    asm volatile("cp.async.cg.shared.global [%0], [%1], 16;" :: "r"(dst), "l"(src));
}
#define CP_COMMIT() asm volatile("cp.async.commit_group;" ::: "memory")
#define CP_WAIT1()  asm volatile("cp.async.wait_group 1;" ::: "memory")

__device__ __forceinline__ void ldsm4(uint32_t* r, uint32_t addr) {
    asm volatile("ldmatrix.sync.aligned.m8n8.x4.shared.b16 {%0,%1,%2,%3}, [%4];"
                 : "=r"(r[0]), "=r"(r[1]), "=r"(r[2]), "=r"(r[3]) : "r"(addr));
}
__device__ __forceinline__ void mma16816(float* d, const uint32_t* a, const uint32_t* b) {
    asm volatile("mma.sync.aligned.m16n8k16.row.col.f32.bf16.bf16.f32 "
                 "{%0,%1,%2,%3}, {%4,%5,%6,%7}, {%8,%9}, {%0,%1,%2,%3};"
                 : "+f"(d[0]), "+f"(d[1]), "+f"(d[2]), "+f"(d[3])
                 : "r"(a[0]), "r"(a[1]), "r"(a[2]), "r"(a[3]), "r"(b[0]), "r"(b[1]));
}

typedef unsigned long long ull;
__device__ __forceinline__ ull ffma2(ull a, ull b, ull c) {
    ull d; asm("fma.rn.f32x2 %0, %1, %2, %3;" : "=l"(d) : "l"(a), "l"(b), "l"(c)); return d;
}
__device__ __forceinline__ ull mul2(ull a, ull b) {
    ull d; asm("mul.rn.f32x2 %0, %1, %2;" : "=l"(d) : "l"(a), "l"(b)); return d;
}
__device__ __forceinline__ ull add2(ull a, ull b) {
    ull d; asm("add.rn.f32x2 %0, %1, %2;" : "=l"(d) : "l"(a), "l"(b)); return d;
}
__device__ __forceinline__ ull dup2(float a) {
    ull r; asm("mov.b64 %0, {%1, %1};" : "=l"(r) : "f"(a)); return r;
}
__device__ __forceinline__ ull pack2(float lo, float hi) {
    ull r; asm("mov.b64 %0, {%1, %2};" : "=l"(r) : "f"(lo), "f"(hi)); return r;
}
__device__ __forceinline__ float2 unpack2(ull v) {
    float2 r; asm("mov.b64 {%0, %1}, %2;" : "=f"(r.x), "=f"(r.y) : "l"(v)); return r;
}
__device__ __forceinline__ ull neg2(ull v) { return v ^ 0x8000000080000000ULL; }

// -------- K0: zero accumulators --------
__global__ void k_zero() {
    int i = blockIdx.x * blockDim.x + threadIdx.x;
    if (i < KCOLS) g_norm2[i] = 0.f;
    if (i < 2 * KCOLS) g_stat[i] = 0.f;
    if (i < NPTS * KCOLS) { g_ecfR[i] = 0.f; g_ecfI[i] = 0.f; }
}

// -------- K1: column squared norms of directions --------
__global__ void k_norm2(const float* __restrict__ dir) {
    int k  = (blockIdx.x & 1) * 256 + threadIdx.x;
    int d0 = (blockIdx.x >> 1) * 32;
    float s = 0.f;
#pragma unroll 8
    for (int d = 0; d < 32; d++) {
        float v = dir[(size_t)(d0 + d) * KCOLS + k];
        s = fmaf(v, v, s);
    }
    atomicAdd(&g_norm2[k], s);
}

// -------- K2: normalize + transpose + bf16 hi/lo split of directions --------
__global__ void __launch_bounds__(256) k_prepB(const float* __restrict__ dir) {
    __shared__ float s[64][65];
    int t = threadIdx.x;
    int n0t = blockIdx.x * 64;
    int d0  = blockIdx.y * 64;
#pragma unroll
    for (int jj = 0; jj < 4; jj++) {
        int flat = jj * 256 + t;
        int d = flat >> 4;
        int nq = flat & 15;
        float4 v = *(const float4*)(dir + (size_t)(d0 + d) * KCOLS + n0t + nq * 4);
        s[d][nq * 4 + 0] = v.x; s[d][nq * 4 + 1] = v.y;
        s[d][nq * 4 + 2] = v.z; s[d][nq * 4 + 3] = v.w;
    }
    __syncthreads();
#pragma unroll
    for (int jj = 0; jj < 4; jj++) {
        int flat = jj * 256 + t;
        int n = flat >> 4;
        int dq = flat & 15;
        float rn = rsqrtf(fmaxf(g_norm2[n0t + n], 1e-24f));
        float x0 = s[dq * 4 + 0][n] * rn, x1 = s[dq * 4 + 1][n] * rn;
        float x2 = s[dq * 4 + 2][n] * rn, x3 = s[dq * 4 + 3][n] * rn;
        __nv_bfloat162 h01 = __floats2bfloat162_rn(x0, x1);
        __nv_bfloat162 h23 = __floats2bfloat162_rn(x2, x3);
        float l0 = x0 - __bfloat162float(h01.x), l1 = x1 - __bfloat162float(h01.y);
        float l2 = x2 - __bfloat162float(h23.x), l3 = x3 - __bfloat162float(h23.y);
        __nv_bfloat162 q01 = __floats2bfloat162_rn(l0, l1);
        __nv_bfloat162 q23 = __floats2bfloat162_rn(l2, l3);
        size_t o = (size_t)(n0t + n) * DDIM + d0 + dq * 4;
        *(uint2*)(g_Bt_hi + o) = make_uint2(*(uint32_t*)&h01, *(uint32_t*)&h23);
        *(uint2*)(g_Bt_lo + o) = make_uint2(*(uint32_t*)&q01, *(uint32_t*)&q23);
    }
}

// -------- K3: split A into bf16 hi/lo --------
__global__ void __launch_bounds__(256) k_prepA(const float* __restrict__ A) {
    size_t idx = ((size_t)blockIdx.x * 256 + threadIdx.x) * 4;
    float4 v = *(const float4*)(A + idx);
    __nv_bfloat162 h01 = __floats2bfloat162_rn(v.x, v.y);
    __nv_bfloat162 h23 = __floats2bfloat162_rn(v.z, v.w);
    float l0 = v.x - __bfloat162float(h01.x), l1 = v.y - __bfloat162float(h01.y);
    float l2 = v.z - __bfloat162float(h23.x), l3 = v.w - __bfloat162float(h23.y);
    __nv_bfloat162 q01 = __floats2bfloat162_rn(l0, l1);
    __nv_bfloat162 q23 = __floats2bfloat162_rn(l2, l3);
    *(uint2*)(g_A_hi + idx) = make_uint2(*(uint32_t*)&h01, *(uint32_t*)&h23);
    *(uint2*)(g_A_lo + idx) = make_uint2(*(uint32_t*)&q01, *(uint32_t*)&q23);
}

// -------- K4: HMMA split-bf16 GEMM with fused column stats --------
__global__ void __launch_bounds__(256, 2) k_gemm(void) {
    extern __shared__ char smem[];
    const uint32_t sbase = smem_u32(smem);
    const int tid  = threadIdx.x;
    const int lane = tid & 31;
    const int wid  = tid >> 5;
    const int wm   = wid >> 2;       // 0..1  (64-row strip)
    const int wn   = wid & 3;        // 0..3  (32-col strip)
    const int n0 = blockIdx.x * BN;
    const int m0 = blockIdx.y * BM;

    const int lrow = tid >> 1;
    const int lcb  = (tid & 1) * 32;
    const int lke  = (tid & 1) * 16;
    const size_t aoff = (size_t)(m0 + lrow) * DDIM + lke;
    const size_t boff = (size_t)(n0 + lrow) * DDIM + lke;
    const uint32_t ldst = lrow * (TSTRIDE * 2) + lcb;

#define ISSUE(stg, ks) do {                                                   \
    uint32_t _d = sbase + (stg) * STAGEB + ldst;                              \
    size_t _k = (size_t)(ks) * BK;                                            \
    cp16(_d + OAH,      g_A_hi  + aoff + _k);                                 \
    cp16(_d + OAH + 16, g_A_hi  + aoff + _k + 8);                             \
    cp16(_d + OAL,      g_A_lo  + aoff + _k);                                 \
    cp16(_d + OAL + 16, g_A_lo  + aoff + _k + 8);                             \
    cp16(_d + OBH,      g_Bt_hi + boff + _k);                                 \
    cp16(_d + OBH + 16, g_Bt_hi + boff + _k + 8);                             \
    cp16(_d + OBL,      g_Bt_lo + boff + _k);                                 \
    cp16(_d + OBL + 16, g_Bt_lo + boff + _k + 8);                             \
} while (0)

    float acc[4][4][4];
#pragma unroll
    for (int i = 0; i < 4; i++)
#pragma unroll
        for (int j = 0; j < 4; j++)
#pragma unroll
            for (int q = 0; q < 4; q++) acc[i][j][q] = 0.f;

    // ldmatrix lane-address components (bytes)
    const uint32_t aRowB = (wm * 64 + (lane & 15)) * (TSTRIDE * 2) + ((lane >> 4) & 1) * 16;
    // x4 B address: matrices {nf k-lo, nf k-hi, nf+1 k-lo, nf+1 k-hi}
    const uint32_t bRow4 = (wn * 32 + ((lane >> 4) & 1) * 8 + (lane & 7)) * (TSTRIDE * 2)
                         + ((lane >> 3) & 1) * 16;

    ISSUE(0, 0); CP_COMMIT();
    ISSUE(1, 1); CP_COMMIT();

    for (int i = 0; i < KITER; i++) {
        CP_WAIT1();
        __syncthreads();
        const uint32_t sb = sbase + (i & 1) * STAGEB;
#pragma unroll
        for (int k16 = 0; k16 < 2; k16++) {
            const uint32_t kb = k16 * 32;
            uint32_t af[4][4], bh[4][2], bl[4][2];
#pragma unroll
            for (int mf = 0; mf < 4; mf++)
                ldsm4(af[mf], sb + OAH + aRowB + mf * 16 * (TSTRIDE * 2) + kb);
#pragma unroll
            for (int p = 0; p < 2; p++) {
                uint32_t tmp[4];
                ldsm4(tmp, sb + OBH + bRow4 + p * 16 * (TSTRIDE * 2) + kb);
                bh[2 * p][0] = tmp[0]; bh[2 * p][1] = tmp[1];
                bh[2 * p + 1][0] = tmp[2]; bh[2 * p + 1][1] = tmp[3];
                ldsm4(tmp, sb + OBL + bRow4 + p * 16 * (TSTRIDE * 2) + kb);
                bl[2 * p][0] = tmp[0]; bl[2 * p][1] = tmp[1];
                bl[2 * p + 1][0] = tmp[2]; bl[2 * p + 1][1] = tmp[3];
            }
#pragma unroll
            for (int mf = 0; mf < 4; mf++)
#pragma unroll
                for (int nf = 0; nf < 4; nf++) {
                    mma16816(acc[mf][nf], af[mf], bh[nf]);
                    mma16816(acc[mf][nf], af[mf], bl[nf]);
                }
#pragma unroll
            for (int mf = 0; mf < 4; mf++)
                ldsm4(af[mf], sb + OAL + aRowB + mf * 16 * (TSTRIDE * 2) + kb);
#pragma unroll
            for (int mf = 0; mf < 4; mf++)
#pragma unroll
                for (int nf = 0; nf < 4; nf++)
                    mma16816(acc[mf][nf], af[mf], bh[nf]);
        }
        __syncthreads();
        if (i + 2 < KITER) ISSUE(i & 1, i + 2);
        CP_COMMIT();
    }

    // ---- epilogue: store proj + fused column stats ----
    float sc[8], sq[8];
#pragma unroll
    for (int e = 0; e < 8; e++) { sc[e] = 0.f; sq[e] = 0.f; }

#pragma unroll
    for (int mf = 0; mf < 4; mf++) {
        const int m = m0 + wm * 64 + mf * 16 + (lane >> 2);
#pragma unroll
        for (int nf = 0; nf < 4; nf++) {
            const int n = n0 + wn * 32 + nf * 8 + (lane & 3) * 2;
            float* c = acc[mf][nf];
            *(float2*)&g_proj[(size_t)m * KCOLS + n]       = make_float2(c[0], c[1]);
            *(float2*)&g_proj[(size_t)(m + 8) * KCOLS + n] = make_float2(c[2], c[3]);
            sc[nf * 2 + 0] += c[0] + c[2];
            sc[nf * 2 + 1] += c[1] + c[3];
            sq[nf * 2 + 0] += c[0] * c[0] + c[2] * c[2];
            sq[nf * 2 + 1] += c[1] * c[1] + c[3] * c[3];
        }
    }
#pragma unroll
    for (int off = 16; off >= 4; off >>= 1)
#pragma unroll
        for (int e = 0; e < 8; e++) {
            sc[e] += __shfl_down_sync(0xFFFFFFFF, sc[e], off);
            sq[e] += __shfl_down_sync(0xFFFFFFFF, sq[e], off);
        }
    if (lane < 4) {
#pragma unroll
        for (int nf = 0; nf < 4; nf++)
#pragma unroll
            for (int p = 0; p < 2; p++) {
                int col = n0 + wn * 32 + nf * 8 + 2 * lane + p;
                atomicAdd(&g_stat[col],         sc[nf * 2 + p]);
                atomicAdd(&g_stat[KCOLS + col], sq[nf * 2 + p]);
            }
    }
}

// -------- K5: a,b affine --------
__global__ void k_ab() {
    int k = blockIdx.x * blockDim.x + threadIdx.x;
    if (k >= KCOLS) return;
    float sum = g_stat[k];
    float sq  = g_stat[KCOLS + k];
    float mu  = sum * (1.0f / (float)BROWS);
    float var = (sq - (float)BROWS * mu * mu) * (1.0f / (float)(BROWS - 1));
    float sd  = sqrtf(fmaxf(var, 0.f));
    float a   = 1.0f / (sd + 1e-8f);
    g_ab[k]         = DT * a;
    g_ab[KCOLS + k] = DT * (-mu * a);
}

// -------- K6: ECF via packed-f32x2 Taylor sin/cos + Chebyshev recurrence --------
// cos((m+1)x) = 2cosx*cos(mx) - cos((m-1)x); same coefficient for sin.
// Per harmonic: 2 FFMA2 (fma pipe) + 2 ADD2 (acc) + 2 XOR (alu pipe, dual-issued).
__global__ void __launch_bounds__(256) k_ecf() {
    __shared__ float part[8][2 * NPTS][32];
    const int lane = threadIdx.x & 31;
    const int w    = threadIdx.x >> 5;
    const int k    = blockIdx.x * 32 + lane;
    const int b0   = blockIdx.y * 512 + w * 64;

    const float a = g_ab[k];
    const float b = g_ab[KCOLS + k];

    const ull ONE = dup2(1.0f);
    const ull NONE = dup2(-1.0f);
    const ull S1 = dup2(-1.6666667e-1f), S2 = dup2(8.3333333e-3f), S3 = dup2(-1.9841270e-4f);
    const ull C1 = dup2(-0.5f), C2 = dup2(4.1666668e-2f), C3 = dup2(-1.3888889e-3f), C4 = dup2(2.4801587e-5f);

    ull accR[NPTS], accI[NPTS];
#pragma unroll
    for (int j = 0; j < NPTS; j++) { accR[j] = 0ULL; accI[j] = 0ULL; }

#pragma unroll 2
    for (int r = 0; r < 32; r++) {
        float pA = g_proj[(size_t)(b0 + r) * KCOLS + k];
        float pB = g_proj[(size_t)(b0 + r + 32) * KCOLS + k];
        ull x  = pack2(fmaf(a, pA, b), fmaf(a, pB, b));
        ull x2 = mul2(x, x);
        ull ps = ffma2(x2, S3, S2); ps = ffma2(x2, ps, S1); ps = ffma2(x2, ps, ONE);
        ull s1 = mul2(x, ps);
        ull pc = ffma2(x2, C4, C3); pc = ffma2(x2, pc, C2); pc = ffma2(x2, pc, C1);
        ull c1 = ffma2(x2, pc, ONE);

        ull twoc = add2(c1, c1);
        ull c = c1, s = s1;
        ull ncp = NONE;            // -cos(0*x)
        ull nsp = 0ULL;            // -sin(0*x) = -0
        accR[0] = add2(accR[0], c1);
        accI[0] = add2(accI[0], s1);
#pragma unroll
        for (int m = 2; m <= NPTS; m++) {
            ull cn = ffma2(twoc, c, ncp);
            ull sn = ffma2(twoc, s, nsp);
            accR[m - 1] = add2(accR[m - 1], cn);
            accI[m - 1] = add2(accI[m - 1], sn);
            ncp = neg2(c); nsp = neg2(s);
            c = cn; s = sn;
        }
    }
#pragma unroll
    for (int j = 0; j < NPTS; j++) {
        float2 fr = unpack2(accR[j]);
        float2 fi = unpack2(accI[j]);
        part[w][j][lane]        = fr.x + fr.y;
        part[w][NPTS + j][lane] = fi.x + fi.y;
    }
    __syncthreads();
    for (int e = threadIdx.x; e < 2 * NPTS * 32; e += 256) {
        int jj = e >> 5;
        int ln = e & 31;
        float s = 0.f;
#pragma unroll
        for (int ww = 0; ww < 8; ww++) s += part[ww][jj][ln];
        int kk = blockIdx.x * 32 + ln;
        if (jj < NPTS) atomicAdd(&g_ecfR[jj * KCOLS + kk], s);
        else           atomicAdd(&g_ecfI[(jj - NPTS) * KCOLS + kk], s);
    }
}

// -------- K7: final scalar --------
__global__ void k_final(float* __restrict__ out) {
    __shared__ float sd[KCOLS];
    int k = threadIdx.x;
    float acc = 0.f;
#pragma unroll
    for (int j = 0; j < NPTS; j++) {
        float t   = (float)(j + 1) * DT;
        float er  = g_ecfR[j * KCOLS + k] * (1.0f / (float)BROWS);
        float ei  = g_ecfI[j * KCOLS + k] * (1.0f / (float)BROWS);
        float tcf = expf(-0.5f * t * t);
        float wq  = (j == 0 || j == NPTS - 1) ? (DT * 0.5f) : DT;
        float d   = er - tcf;
        acc = fmaf(wq, fmaf(d, d, ei * ei), acc);
    }
    sd[k] = acc;
    __syncthreads();
    for (int s = 256; s > 0; s >>= 1) {
        if (k < s) sd[k] += sd[k + s];
        __syncthreads();
    }
    if (k == 0) out[0] = sd[0] * (1.0f / (float)KCOLS);
}

extern "C" void kernel_launch(void* const* d_in, const int* in_sizes, int n_in,
                              void* d_out, int out_size) {
    const float* emb = (const float*)d_in[0];   // (8192, 2048)
    const float* dir = (const float*)d_in[1];   // (2048, 512)
    float* out = (float*)d_out;

    cudaFuncSetAttribute(k_gemm, cudaFuncAttributeMaxDynamicSharedMemorySize, GEMM_SMEM);

    k_zero<<<(NPTS * KCOLS + 255) / 256, 256>>>();
    k_norm2<<<128, 256>>>(dir);
    k_prepB<<<dim3(KCOLS / 64, DDIM / 64), 256>>>(dir);
    k_prepA<<<(BROWS * DDIM) / (256 * 4), 256>>>(emb);
    k_gemm<<<dim3(KCOLS / BN, BROWS / BM), 256, GEMM_SMEM>>>();
    k_ab<<<2, 256>>>();
    k_ecf<<<dim3(KCOLS / 32, BROWS / 512), 256>>>();
    k_final<<<1, KCOLS>>>(out);
}

// round 6
// speedup vs baseline: 2.7550x; 1.3719x over previous
#include <cuda_runtime.h>
#include <cuda_bf16.h>
#include <cstdint>

#define BROWS 8192
#define DDIM  2048
#define KCOLS 512
#define NPTS  17
#define DT    (2.0f / 17.0f)

// ---- GEMM tiling ----
#define BM 128
#define BN 128
#define BK 32
#define KITER (DDIM / BK)          // 64
#define TSTRIDE 40                 // bf16 halves per smem row (32 data + 8 pad)
#define TILEB (128 * TSTRIDE * 2)  // 10240 bytes per tile
#define OAH 0
#define OBH (1 * TILEB)
#define OBL (2 * TILEB)
#define STAGEB (3 * TILEB)         // 30720 bytes per stage
#define GEMM_SMEM (2 * STAGEB)     // 61440

// ---- device scratch ----
__device__ float g_norm2[KCOLS];
__device__ __nv_bfloat16 g_A_hi[(size_t)BROWS * DDIM];
__device__ __nv_bfloat16 g_Bt_hi[KCOLS * DDIM];   // [n][k] normalized, hi
__device__ __nv_bfloat16 g_Bt_lo[KCOLS * DDIM];   // [n][k] residual, lo
__device__ float g_proj[(size_t)BROWS * KCOLS];
__device__ float g_stat[2 * KCOLS];
__device__ float g_ab[2 * KCOLS];
__device__ float g_ecfR[NPTS * KCOLS];
__device__ float g_ecfI[NPTS * KCOLS];

// ---- helpers ----
__device__ __forceinline__ uint32_t smem_u32(const void* p) {
    uint32_t a;
    asm("{ .reg .u64 t; cvta.to.shared.u64 t, %1; cvt.u32.u64 %0, t; }" : "=r"(a) : "l"(p));
    return a;
}
__device__ __forceinline__ void cp16(uint32_t dst, const void* src) {
    asm volatile("cp.async.cg.shared.global [%0], [%1], 16;" :: "r"(dst), "l"(src));
}
#define CP_COMMIT() asm volatile("cp.async.commit_group;" ::: "memory")
#define CP_WAIT1()  asm volatile("cp.async.wait_group 1;" ::: "memory")

__device__ __forceinline__ void ldsm4(uint32_t* r, uint32_t addr) {
    asm volatile("ldmatrix.sync.aligned.m8n8.x4.shared.b16 {%0,%1,%2,%3}, [%4];"
                 : "=r"(r[0]), "=r"(r[1]), "=r"(r[2]), "=r"(r[3]) : "r"(addr));
}
__device__ __forceinline__ void mma16816(float* d, const uint32_t* a, const uint32_t* b) {
    asm volatile("mma.sync.aligned.m16n8k16.row.col.f32.bf16.bf16.f32 "
                 "{%0,%1,%2,%3}, {%4,%5,%6,%7}, {%8,%9}, {%0,%1,%2,%3};"
                 : "+f"(d[0]), "+f"(d[1]), "+f"(d[2]), "+f"(d[3])
                 : "r"(a[0]), "r"(a[1]), "r"(a[2]), "r"(a[3]), "r"(b[0]), "r"(b[1]));
}

typedef unsigned long long ull;
__device__ __forceinline__ ull ffma2(ull a, ull b, ull c) {
    ull d; asm("fma.rn.f32x2 %0, %1, %2, %3;" : "=l"(d) : "l"(a), "l"(b), "l"(c)); return d;
}
__device__ __forceinline__ ull mul2(ull a, ull b) {
    ull d; asm("mul.rn.f32x2 %0, %1, %2;" : "=l"(d) : "l"(a), "l"(b)); return d;
}
__device__ __forceinline__ ull add2(ull a, ull b) {
    ull d; asm("add.rn.f32x2 %0, %1, %2;" : "=l"(d) : "l"(a), "l"(b)); return d;
}
__device__ __forceinline__ ull dup2(float a) {
    ull r; asm("mov.b64 %0, {%1, %1};" : "=l"(r) : "f"(a)); return r;
}
__device__ __forceinline__ ull pack2(float lo, float hi) {
    ull r; asm("mov.b64 %0, {%1, %2};" : "=l"(r) : "f"(lo), "f"(hi)); return r;
}
__device__ __forceinline__ float2 unpack2(ull v) {
    float2 r; asm("mov.b64 {%0, %1}, %2;" : "=f"(r.x), "=f"(r.y) : "l"(v)); return r;
}
__device__ __forceinline__ ull neg2(ull v) { return v ^ 0x8000000080000000ULL; }

// -------- K0: zero accumulators --------
__global__ void k_zero() {
    int i = blockIdx.x * blockDim.x + threadIdx.x;
    if (i < KCOLS) g_norm2[i] = 0.f;
    if (i < 2 * KCOLS) g_stat[i] = 0.f;
    if (i < NPTS * KCOLS) { g_ecfR[i] = 0.f; g_ecfI[i] = 0.f; }
}

// -------- K1: column squared norms of directions --------
__global__ void k_norm2(const float* __restrict__ dir) {
    int k  = (blockIdx.x & 1) * 256 + threadIdx.x;
    int d0 = (blockIdx.x >> 1) * 32;
    float s = 0.f;
#pragma unroll 8
    for (int d = 0; d < 32; d++) {
        float v = dir[(size_t)(d0 + d) * KCOLS + k];
        s = fmaf(v, v, s);
    }
    atomicAdd(&g_norm2[k], s);
}

// -------- K2: normalize + transpose + bf16 hi/lo split of directions --------
__global__ void __launch_bounds__(256) k_prepB(const float* __restrict__ dir) {
    __shared__ float s[64][65];
    int t = threadIdx.x;
    int n0t = blockIdx.x * 64;
    int d0  = blockIdx.y * 64;
#pragma unroll
    for (int jj = 0; jj < 4; jj++) {
        int flat = jj * 256 + t;
        int d = flat >> 4;
        int nq = flat & 15;
        float4 v = *(const float4*)(dir + (size_t)(d0 + d) * KCOLS + n0t + nq * 4);
        s[d][nq * 4 + 0] = v.x; s[d][nq * 4 + 1] = v.y;
        s[d][nq * 4 + 2] = v.z; s[d][nq * 4 + 3] = v.w;
    }
    __syncthreads();
#pragma unroll
    for (int jj = 0; jj < 4; jj++) {
        int flat = jj * 256 + t;
        int n = flat >> 4;
        int dq = flat & 15;
        float rn = rsqrtf(fmaxf(g_norm2[n0t + n], 1e-24f));
        float x0 = s[dq * 4 + 0][n] * rn, x1 = s[dq * 4 + 1][n] * rn;
        float x2 = s[dq * 4 + 2][n] * rn, x3 = s[dq * 4 + 3][n] * rn;
        __nv_bfloat162 h01 = __floats2bfloat162_rn(x0, x1);
        __nv_bfloat162 h23 = __floats2bfloat162_rn(x2, x3);
        float l0 = x0 - __bfloat162float(h01.x), l1 = x1 - __bfloat162float(h01.y);
        float l2 = x2 - __bfloat162float(h23.x), l3 = x3 - __bfloat162float(h23.y);
        __nv_bfloat162 q01 = __floats2bfloat162_rn(l0, l1);
        __nv_bfloat162 q23 = __floats2bfloat162_rn(l2, l3);
        size_t o = (size_t)(n0t + n) * DDIM + d0 + dq * 4;
        *(uint2*)(g_Bt_hi + o) = make_uint2(*(uint32_t*)&h01, *(uint32_t*)&h23);
        *(uint2*)(g_Bt_lo + o) = make_uint2(*(uint32_t*)&q01, *(uint32_t*)&q23);
    }
}

// -------- K3: split A into bf16 hi (lo term dropped — see error analysis) --------
__global__ void __launch_bounds__(256) k_prepA(const float* __restrict__ A) {
    size_t idx = ((size_t)blockIdx.x * 256 + threadIdx.x) * 8;
    float4 v0 = *(const float4*)(A + idx);
    float4 v1 = *(const float4*)(A + idx + 4);
    __nv_bfloat162 h01 = __floats2bfloat162_rn(v0.x, v0.y);
    __nv_bfloat162 h23 = __floats2bfloat162_rn(v0.z, v0.w);
    __nv_bfloat162 h45 = __floats2bfloat162_rn(v1.x, v1.y);
    __nv_bfloat162 h67 = __floats2bfloat162_rn(v1.z, v1.w);
    *(uint4*)(g_A_hi + idx) = make_uint4(*(uint32_t*)&h01, *(uint32_t*)&h23,
                                         *(uint32_t*)&h45, *(uint32_t*)&h67);
}

// -------- K4: HMMA GEMM (Ah·Bh + Ah·Bl) with fused column stats --------
__global__ void __launch_bounds__(256, 2) k_gemm(void) {
    extern __shared__ char smem[];
    const uint32_t sbase = smem_u32(smem);
    const int tid  = threadIdx.x;
    const int lane = tid & 31;
    const int wid  = tid >> 5;
    const int wm   = wid >> 2;       // 0..1  (64-row strip)
    const int wn   = wid & 3;        // 0..3  (32-col strip)
    const int n0 = blockIdx.x * BN;
    const int m0 = blockIdx.y * BM;

    const int lrow = tid >> 1;
    const int lcb  = (tid & 1) * 32;
    const int lke  = (tid & 1) * 16;
    const size_t aoff = (size_t)(m0 + lrow) * DDIM + lke;
    const size_t boff = (size_t)(n0 + lrow) * DDIM + lke;
    const uint32_t ldst = lrow * (TSTRIDE * 2) + lcb;

#define ISSUE(stg, ks) do {                                                   \
    uint32_t _d = sbase + (stg) * STAGEB + ldst;                              \
    size_t _k = (size_t)(ks) * BK;                                            \
    cp16(_d + OAH,      g_A_hi  + aoff + _k);                                 \
    cp16(_d + OAH + 16, g_A_hi  + aoff + _k + 8);                             \
    cp16(_d + OBH,      g_Bt_hi + boff + _k);                                 \
    cp16(_d + OBH + 16, g_Bt_hi + boff + _k + 8);                             \
    cp16(_d + OBL,      g_Bt_lo + boff + _k);                                 \
    cp16(_d + OBL + 16, g_Bt_lo + boff + _k + 8);                             \
} while (0)

    float acc[4][4][4];
#pragma unroll
    for (int i = 0; i < 4; i++)
#pragma unroll
        for (int j = 0; j < 4; j++)
#pragma unroll
            for (int q = 0; q < 4; q++) acc[i][j][q] = 0.f;

    const uint32_t aRowB = (wm * 64 + (lane & 15)) * (TSTRIDE * 2) + ((lane >> 4) & 1) * 16;
    const uint32_t bRow4 = (wn * 32 + ((lane >> 4) & 1) * 8 + (lane & 7)) * (TSTRIDE * 2)
                         + ((lane >> 3) & 1) * 16;

    ISSUE(0, 0); CP_COMMIT();
    ISSUE(1, 1); CP_COMMIT();

    for (int i = 0; i < KITER; i++) {
        CP_WAIT1();
        __syncthreads();
        const uint32_t sb = sbase + (i & 1) * STAGEB;
#pragma unroll
        for (int k16 = 0; k16 < 2; k16++) {
            const uint32_t kb = k16 * 32;
            uint32_t af[4][4], bh[4][2], bl[4][2];
#pragma unroll
            for (int mf = 0; mf < 4; mf++)
                ldsm4(af[mf], sb + OAH + aRowB + mf * 16 * (TSTRIDE * 2) + kb);
#pragma unroll
            for (int p = 0; p < 2; p++) {
                uint32_t tmp[4];
                ldsm4(tmp, sb + OBH + bRow4 + p * 16 * (TSTRIDE * 2) + kb);
                bh[2 * p][0] = tmp[0]; bh[2 * p][1] = tmp[1];
                bh[2 * p + 1][0] = tmp[2]; bh[2 * p + 1][1] = tmp[3];
                ldsm4(tmp, sb + OBL + bRow4 + p * 16 * (TSTRIDE * 2) + kb);
                bl[2 * p][0] = tmp[0]; bl[2 * p][1] = tmp[1];
                bl[2 * p + 1][0] = tmp[2]; bl[2 * p + 1][1] = tmp[3];
            }
#pragma unroll
            for (int mf = 0; mf < 4; mf++)
#pragma unroll
                for (int nf = 0; nf < 4; nf++) {
                    mma16816(acc[mf][nf], af[mf], bh[nf]);
                    mma16816(acc[mf][nf], af[mf], bl[nf]);
                }
        }
        __syncthreads();
        if (i + 2 < KITER) ISSUE(i & 1, i + 2);
        CP_COMMIT();
    }

    // ---- epilogue: store proj + fused column stats ----
    float sc[8], sq[8];
#pragma unroll
    for (int e = 0; e < 8; e++) { sc[e] = 0.f; sq[e] = 0.f; }

#pragma unroll
    for (int mf = 0; mf < 4; mf++) {
        const int m = m0 + wm * 64 + mf * 16 + (lane >> 2);
#pragma unroll
        for (int nf = 0; nf < 4; nf++) {
            const int n = n0 + wn * 32 + nf * 8 + (lane & 3) * 2;
            float* c = acc[mf][nf];
            *(float2*)&g_proj[(size_t)m * KCOLS + n]       = make_float2(c[0], c[1]);
            *(float2*)&g_proj[(size_t)(m + 8) * KCOLS + n] = make_float2(c[2], c[3]);
            sc[nf * 2 + 0] += c[0] + c[2];
            sc[nf * 2 + 1] += c[1] + c[3];
            sq[nf * 2 + 0] += c[0] * c[0] + c[2] * c[2];
            sq[nf * 2 + 1] += c[1] * c[1] + c[3] * c[3];
        }
    }
#pragma unroll
    for (int off = 16; off >= 4; off >>= 1)
#pragma unroll
        for (int e = 0; e < 8; e++) {
            sc[e] += __shfl_down_sync(0xFFFFFFFF, sc[e], off);
            sq[e] += __shfl_down_sync(0xFFFFFFFF, sq[e], off);
        }
    if (lane < 4) {
#pragma unroll
        for (int nf = 0; nf < 4; nf++)
#pragma unroll
            for (int p = 0; p < 2; p++) {
                int col = n0 + wn * 32 + nf * 8 + 2 * lane + p;
                atomicAdd(&g_stat[col],         sc[nf * 2 + p]);
                atomicAdd(&g_stat[KCOLS + col], sq[nf * 2 + p]);
            }
    }
}

// -------- K5: a,b affine --------
__global__ void k_ab() {
    int k = blockIdx.x * blockDim.x + threadIdx.x;
    if (k >= KCOLS) return;
    float sum = g_stat[k];
    float sq  = g_stat[KCOLS + k];
    float mu  = sum * (1.0f / (float)BROWS);
    float var = (sq - (float)BROWS * mu * mu) * (1.0f / (float)(BROWS - 1));
    float sd  = sqrtf(fmaxf(var, 0.f));
    float a   = 1.0f / (sd + 1e-8f);
    g_ab[k]         = DT * a;
    g_ab[KCOLS + k] = DT * (-mu * a);
}

// -------- K6: ECF, Chebyshev recurrence with 2 packed chain sets (4 rows/iter) --------
__global__ void __launch_bounds__(256) k_ecf() {
    __shared__ float part[8][2 * NPTS][32];
    const int lane = threadIdx.x & 31;
    const int w    = threadIdx.x >> 5;
    const int k    = blockIdx.x * 32 + lane;
    const int b0   = blockIdx.y * 512 + w * 64;

    const float a = g_ab[k];
    const float b = g_ab[KCOLS + k];

    const ull ONE = dup2(1.0f);
    const ull NONE = dup2(-1.0f);
    const ull S1 = dup2(-1.6666667e-1f), S2 = dup2(8.3333333e-3f), S3 = dup2(-1.9841270e-4f);
    const ull C1 = dup2(-0.5f), C2 = dup2(4.1666668e-2f), C3 = dup2(-1.3888889e-3f), C4 = dup2(2.4801587e-5f);

    ull accR[NPTS], accI[NPTS];
#pragma unroll
    for (int j = 0; j < NPTS; j++) { accR[j] = 0ULL; accI[j] = 0ULL; }

    for (int r = 0; r < 16; r++) {
        float p0 = g_proj[(size_t)(b0 + r)      * KCOLS + k];
        float p1 = g_proj[(size_t)(b0 + r + 16) * KCOLS + k];
        float p2 = g_proj[(size_t)(b0 + r + 32) * KCOLS + k];
        float p3 = g_proj[(size_t)(b0 + r + 48) * KCOLS + k];
        ull xA  = pack2(fmaf(a, p0, b), fmaf(a, p1, b));
        ull xB  = pack2(fmaf(a, p2, b), fmaf(a, p3, b));
        ull x2A = mul2(xA, xA);
        ull x2B = mul2(xB, xB);
        ull psA = ffma2(x2A, S3, S2); psA = ffma2(x2A, psA, S1); psA = ffma2(x2A, psA, ONE);
        ull psB = ffma2(x2B, S3, S2); psB = ffma2(x2B, psB, S1); psB = ffma2(x2B, psB, ONE);
        ull s1A = mul2(xA, psA);
        ull s1B = mul2(xB, psB);
        ull pcA = ffma2(x2A, C4, C3); pcA = ffma2(x2A, pcA, C2); pcA = ffma2(x2A, pcA, C1);
        ull pcB = ffma2(x2B, C4, C3); pcB = ffma2(x2B, pcB, C2); pcB = ffma2(x2B, pcB, C1);
        ull c1A = ffma2(x2A, pcA, ONE);
        ull c1B = ffma2(x2B, pcB, ONE);

        ull twocA = add2(c1A, c1A), twocB = add2(c1B, c1B);
        ull cA = c1A, sA = s1A, cB = c1B, sB = s1B;
        ull ncpA = NONE, nspA = 0ULL, ncpB = NONE, nspB = 0ULL;
        accR[0] = add2(accR[0], add2(c1A, c1B));
        accI[0] = add2(accI[0], add2(s1A, s1B));
#pragma unroll
        for (int m = 2; m <= NPTS; m++) {
            ull cnA = ffma2(twocA, cA, ncpA);
            ull snA = ffma2(twocA, sA, nspA);
            ull cnB = ffma2(twocB, cB, ncpB);
            ull snB = ffma2(twocB, sB, nspB);
            accR[m - 1] = add2(accR[m - 1], add2(cnA, cnB));
            accI[m - 1] = add2(accI[m - 1], add2(snA, snB));
            ncpA = neg2(cA); nspA = neg2(sA);
            ncpB = neg2(cB); nspB = neg2(sB);
            cA = cnA; sA = snA; cB = cnB; sB = snB;
        }
    }
#pragma unroll
    for (int j = 0; j < NPTS; j++) {
        float2 fr = unpack2(accR[j]);
        float2 fi = unpack2(accI[j]);
        part[w][j][lane]        = fr.x + fr.y;
        part[w][NPTS + j][lane] = fi.x + fi.y;
    }
    __syncthreads();
    for (int e = threadIdx.x; e < 2 * NPTS * 32; e += 256) {
        int jj = e >> 5;
        int ln = e & 31;
        float s = 0.f;
#pragma unroll
        for (int ww = 0; ww < 8; ww++) s += part[ww][jj][ln];
        int kk = blockIdx.x * 32 + ln;
        if (jj < NPTS) atomicAdd(&g_ecfR[jj * KCOLS + kk], s);
        else           atomicAdd(&g_ecfI[(jj - NPTS) * KCOLS + kk], s);
    }
}

// -------- K7: final scalar --------
__global__ void k_final(float* __restrict__ out) {
    __shared__ float sd[KCOLS];
    int k = threadIdx.x;
    float acc = 0.f;
#pragma unroll
    for (int j = 0; j < NPTS; j++) {
        float t   = (float)(j + 1) * DT;
        float er  = g_ecfR[j * KCOLS + k] * (1.0f / (float)BROWS);
        float ei  = g_ecfI[j * KCOLS + k] * (1.0f / (float)BROWS);
        float tcf = expf(-0.5f * t * t);
        float wq  = (j == 0 || j == NPTS - 1) ? (DT * 0.5f) : DT;
        float d   = er - tcf;
        acc = fmaf(wq, fmaf(d, d, ei * ei), acc);
    }
    sd[k] = acc;
    __syncthreads();
    for (int s = 256; s > 0; s >>= 1) {
        if (k < s) sd[k] += sd[k + s];
        __syncthreads();
    }
    if (k == 0) out[0] = sd[0] * (1.0f / (float)KCOLS);
}

extern "C" void kernel_launch(void* const* d_in, const int* in_sizes, int n_in,
                              void* d_out, int out_size) {
    const float* emb = (const float*)d_in[0];   // (8192, 2048)
    const float* dir = (const float*)d_in[1];   // (2048, 512)
    float* out = (float*)d_out;

    cudaFuncSetAttribute(k_gemm, cudaFuncAttributeMaxDynamicSharedMemorySize, GEMM_SMEM);

    k_zero<<<(NPTS * KCOLS + 255) / 256, 256>>>();
    k_norm2<<<128, 256>>>(dir);
    k_prepB<<<dim3(KCOLS / 64, DDIM / 64), 256>>>(dir);
    k_prepA<<<(BROWS * DDIM) / (256 * 8), 256>>>(emb);
    k_gemm<<<dim3(KCOLS / BN, BROWS / BM), 256, GEMM_SMEM>>>();
    k_ab<<<2, 256>>>();
    k_ecf<<<dim3(KCOLS / 32, BROWS / 512), 256>>>();
    k_final<<<1, KCOLS>>>(out);
}

// round 7
// speedup vs baseline: 3.4548x; 1.2540x over previous
#include <cuda_runtime.h>
#include <cuda_bf16.h>
#include <cstdint>

#define BROWS 8192
#define DDIM  2048
#define KCOLS 512
#define NPTS  17
#define DT    (2.0f / 17.0f)

// ---- GEMM tiling ----
#define BM 128
#define BN 128
#define BK 32
#define KITER (DDIM / BK)          // 64
#define TSTRIDE 40                 // bf16 halves per smem row (32 data + 8 pad)
#define TILEB (128 * TSTRIDE * 2)  // 10240 bytes per tile
#define OAH 0
#define OBH (1 * TILEB)
#define STAGEB (2 * TILEB)         // 20480 bytes per stage
#define NSTAGE 3
#define GEMM_SMEM (NSTAGE * STAGEB)  // 61440

// ---- device scratch ----
__device__ float g_norm2[KCOLS];
__device__ __nv_bfloat16 g_A_hi[(size_t)BROWS * DDIM];
__device__ __nv_bfloat16 g_Bt_hi[KCOLS * DDIM];   // [n][k] normalized bf16
__device__ float g_proj[(size_t)BROWS * KCOLS];
__device__ float g_stat[2 * KCOLS];
__device__ float g_ab[2 * KCOLS];
__device__ float g_ecfR[NPTS * KCOLS];
__device__ float g_ecfI[NPTS * KCOLS];

// ---- helpers ----
__device__ __forceinline__ uint32_t smem_u32(const void* p) {
    uint32_t a;
    asm("{ .reg .u64 t; cvta.to.shared.u64 t, %1; cvt.u32.u64 %0, t; }" : "=r"(a) : "l"(p));
    return a;
}
__device__ __forceinline__ void cp16(uint32_t dst, const void* src) {
    asm volatile("cp.async.cg.shared.global [%0], [%1], 16;" :: "r"(dst), "l"(src));
}
#define CP_COMMIT() asm volatile("cp.async.commit_group;" ::: "memory")
#define CP_WAIT1()  asm volatile("cp.async.wait_group 1;" ::: "memory")

__device__ __forceinline__ void ldsm4(uint32_t* r, uint32_t addr) {
    asm volatile("ldmatrix.sync.aligned.m8n8.x4.shared.b16 {%0,%1,%2,%3}, [%4];"
                 : "=r"(r[0]), "=r"(r[1]), "=r"(r[2]), "=r"(r[3]) : "r"(addr));
}
__device__ __forceinline__ void mma16816(float* d, const uint32_t* a, const uint32_t* b) {
    asm volatile("mma.sync.aligned.m16n8k16.row.col.f32.bf16.bf16.f32 "
                 "{%0,%1,%2,%3}, {%4,%5,%6,%7}, {%8,%9}, {%0,%1,%2,%3};"
                 : "+f"(d[0]), "+f"(d[1]), "+f"(d[2]), "+f"(d[3])
                 : "r"(a[0]), "r"(a[1]), "r"(a[2]), "r"(a[3]), "r"(b[0]), "r"(b[1]));
}

typedef unsigned long long ull;
__device__ __forceinline__ ull ffma2(ull a, ull b, ull c) {
    ull d; asm("fma.rn.f32x2 %0, %1, %2, %3;" : "=l"(d) : "l"(a), "l"(b), "l"(c)); return d;
}
__device__ __forceinline__ ull mul2(ull a, ull b) {
    ull d; asm("mul.rn.f32x2 %0, %1, %2;" : "=l"(d) : "l"(a), "l"(b)); return d;
}
__device__ __forceinline__ ull add2(ull a, ull b) {
    ull d; asm("add.rn.f32x2 %0, %1, %2;" : "=l"(d) : "l"(a), "l"(b)); return d;
}
__device__ __forceinline__ ull dup2(float a) {
    ull r; asm("mov.b64 %0, {%1, %1};" : "=l"(r) : "f"(a)); return r;
}
__device__ __forceinline__ ull pack2(float lo, float hi) {
    ull r; asm("mov.b64 %0, {%1, %2};" : "=l"(r) : "f"(lo), "f"(hi)); return r;
}
__device__ __forceinline__ float2 unpack2(ull v) {
    float2 r; asm("mov.b64 {%0, %1}, %2;" : "=f"(r.x), "=f"(r.y) : "l"(v)); return r;
}
__device__ __forceinline__ ull neg2(ull v) { return v ^ 0x8000000080000000ULL; }

// -------- K0: zero accumulators --------
__global__ void k_zero() {
    int i = blockIdx.x * blockDim.x + threadIdx.x;
    if (i < KCOLS) g_norm2[i] = 0.f;
    if (i < 2 * KCOLS) g_stat[i] = 0.f;
    if (i < NPTS * KCOLS) { g_ecfR[i] = 0.f; g_ecfI[i] = 0.f; }
}

// -------- K1: column squared norms of directions --------
__global__ void k_norm2(const float* __restrict__ dir) {
    int k  = (blockIdx.x & 1) * 256 + threadIdx.x;
    int d0 = (blockIdx.x >> 1) * 32;
    float s = 0.f;
#pragma unroll 8
    for (int d = 0; d < 32; d++) {
        float v = dir[(size_t)(d0 + d) * KCOLS + k];
        s = fmaf(v, v, s);
    }
    atomicAdd(&g_norm2[k], s);
}

// -------- K2: normalize + transpose + bf16 round of directions --------
__global__ void __launch_bounds__(256) k_prepB(const float* __restrict__ dir) {
    __shared__ float s[64][65];
    int t = threadIdx.x;
    int n0t = blockIdx.x * 64;
    int d0  = blockIdx.y * 64;
#pragma unroll
    for (int jj = 0; jj < 4; jj++) {
        int flat = jj * 256 + t;
        int d = flat >> 4;
        int nq = flat & 15;
        float4 v = *(const float4*)(dir + (size_t)(d0 + d) * KCOLS + n0t + nq * 4);
        s[d][nq * 4 + 0] = v.x; s[d][nq * 4 + 1] = v.y;
        s[d][nq * 4 + 2] = v.z; s[d][nq * 4 + 3] = v.w;
    }
    __syncthreads();
#pragma unroll
    for (int jj = 0; jj < 4; jj++) {
        int flat = jj * 256 + t;
        int n = flat >> 4;
        int dq = flat & 15;
        float rn = rsqrtf(fmaxf(g_norm2[n0t + n], 1e-24f));
        float x0 = s[dq * 4 + 0][n] * rn, x1 = s[dq * 4 + 1][n] * rn;
        float x2 = s[dq * 4 + 2][n] * rn, x3 = s[dq * 4 + 3][n] * rn;
        __nv_bfloat162 h01 = __floats2bfloat162_rn(x0, x1);
        __nv_bfloat162 h23 = __floats2bfloat162_rn(x2, x3);
        size_t o = (size_t)(n0t + n) * DDIM + d0 + dq * 4;
        *(uint2*)(g_Bt_hi + o) = make_uint2(*(uint32_t*)&h01, *(uint32_t*)&h23);
    }
}

// -------- K3: round A to bf16 --------
__global__ void __launch_bounds__(256) k_prepA(const float* __restrict__ A) {
    size_t idx = ((size_t)blockIdx.x * 256 + threadIdx.x) * 8;
    float4 v0 = *(const float4*)(A + idx);
    float4 v1 = *(const float4*)(A + idx + 4);
    __nv_bfloat162 h01 = __floats2bfloat162_rn(v0.x, v0.y);
    __nv_bfloat162 h23 = __floats2bfloat162_rn(v0.z, v0.w);
    __nv_bfloat162 h45 = __floats2bfloat162_rn(v1.x, v1.y);
    __nv_bfloat162 h67 = __floats2bfloat162_rn(v1.z, v1.w);
    *(uint4*)(g_A_hi + idx) = make_uint4(*(uint32_t*)&h01, *(uint32_t*)&h23,
                                         *(uint32_t*)&h45, *(uint32_t*)&h67);
}

// -------- K4: HMMA bf16 GEMM (single product) with fused column stats --------
__global__ void __launch_bounds__(256, 2) k_gemm(void) {
    extern __shared__ char smem[];
    const uint32_t sbase = smem_u32(smem);
    const int tid  = threadIdx.x;
    const int lane = tid & 31;
    const int wid  = tid >> 5;
    const int wm   = wid >> 2;       // 0..1  (64-row strip)
    const int wn   = wid & 3;        // 0..3  (32-col strip)
    const int n0 = blockIdx.x * BN;
    const int m0 = blockIdx.y * BM;

    const int lrow = tid >> 1;
    const int lcb  = (tid & 1) * 32;
    const int lke  = (tid & 1) * 16;
    const size_t aoff = (size_t)(m0 + lrow) * DDIM + lke;
    const size_t boff = (size_t)(n0 + lrow) * DDIM + lke;
    const uint32_t ldst = lrow * (TSTRIDE * 2) + lcb;

#define ISSUE(stg, ks) do {                                                   \
    uint32_t _d = sbase + (stg) * STAGEB + ldst;                              \
    size_t _k = (size_t)(ks) * BK;                                            \
    cp16(_d + OAH,      g_A_hi  + aoff + _k);                                 \
    cp16(_d + OAH + 16, g_A_hi  + aoff + _k + 8);                             \
    cp16(_d + OBH,      g_Bt_hi + boff + _k);                                 \
    cp16(_d + OBH + 16, g_Bt_hi + boff + _k + 8);                             \
} while (0)

    float acc[4][4][4];
#pragma unroll
    for (int i = 0; i < 4; i++)
#pragma unroll
        for (int j = 0; j < 4; j++)
#pragma unroll
            for (int q = 0; q < 4; q++) acc[i][j][q] = 0.f;

    const uint32_t aRowB = (wm * 64 + (lane & 15)) * (TSTRIDE * 2) + ((lane >> 4) & 1) * 16;
    const uint32_t bRow4 = (wn * 32 + ((lane >> 4) & 1) * 8 + (lane & 7)) * (TSTRIDE * 2)
                         + ((lane >> 3) & 1) * 16;

    ISSUE(0, 0); CP_COMMIT();
    ISSUE(1, 1); CP_COMMIT();

    for (int i = 0; i < KITER; i++) {
        CP_WAIT1();
        __syncthreads();
        // prefetch into the third slot while computing this one
        if (i + 2 < KITER) {
            int slot = (i + 2) % NSTAGE;
            ISSUE(slot, i + 2);
        }
        CP_COMMIT();
        const uint32_t sb = sbase + (i % NSTAGE) * STAGEB;
#pragma unroll
        for (int k16 = 0; k16 < 2; k16++) {
            const uint32_t kb = k16 * 32;
            uint32_t af[4][4], bh[4][2];
#pragma unroll
            for (int mf = 0; mf < 4; mf++)
                ldsm4(af[mf], sb + OAH + aRowB + mf * 16 * (TSTRIDE * 2) + kb);
#pragma unroll
            for (int p = 0; p < 2; p++) {
                uint32_t tmp[4];
                ldsm4(tmp, sb + OBH + bRow4 + p * 16 * (TSTRIDE * 2) + kb);
                bh[2 * p][0] = tmp[0]; bh[2 * p][1] = tmp[1];
                bh[2 * p + 1][0] = tmp[2]; bh[2 * p + 1][1] = tmp[3];
            }
#pragma unroll
            for (int mf = 0; mf < 4; mf++)
#pragma unroll
                for (int nf = 0; nf < 4; nf++)
                    mma16816(acc[mf][nf], af[mf], bh[nf]);
        }
    }

    // ---- epilogue: store proj + fused column stats ----
    float sc[8], sq[8];
#pragma unroll
    for (int e = 0; e < 8; e++) { sc[e] = 0.f; sq[e] = 0.f; }

#pragma unroll
    for (int mf = 0; mf < 4; mf++) {
        const int m = m0 + wm * 64 + mf * 16 + (lane >> 2);
#pragma unroll
        for (int nf = 0; nf < 4; nf++) {
            const int n = n0 + wn * 32 + nf * 8 + (lane & 3) * 2;
            float* c = acc[mf][nf];
            *(float2*)&g_proj[(size_t)m * KCOLS + n]       = make_float2(c[0], c[1]);
            *(float2*)&g_proj[(size_t)(m + 8) * KCOLS + n] = make_float2(c[2], c[3]);
            sc[nf * 2 + 0] += c[0] + c[2];
            sc[nf * 2 + 1] += c[1] + c[3];
            sq[nf * 2 + 0] += c[0] * c[0] + c[2] * c[2];
            sq[nf * 2 + 1] += c[1] * c[1] + c[3] * c[3];
        }
    }
#pragma unroll
    for (int off = 16; off >= 4; off >>= 1)
#pragma unroll
        for (int e = 0; e < 8; e++) {
            sc[e] += __shfl_down_sync(0xFFFFFFFF, sc[e], off);
            sq[e] += __shfl_down_sync(0xFFFFFFFF, sq[e], off);
        }
    if (lane < 4) {
#pragma unroll
        for (int nf = 0; nf < 4; nf++)
#pragma unroll
            for (int p = 0; p < 2; p++) {
                int col = n0 + wn * 32 + nf * 8 + 2 * lane + p;
                atomicAdd(&g_stat[col],         sc[nf * 2 + p]);
                atomicAdd(&g_stat[KCOLS + col], sq[nf * 2 + p]);
            }
    }
}

// -------- K5: a,b affine --------
__global__ void k_ab() {
    int k = blockIdx.x * blockDim.x + threadIdx.x;
    if (k >= KCOLS) return;
    float sum = g_stat[k];
    float sq  = g_stat[KCOLS + k];
    float mu  = sum * (1.0f / (float)BROWS);
    float var = (sq - (float)BROWS * mu * mu) * (1.0f / (float)(BROWS - 1));
    float sd  = sqrtf(fmaxf(var, 0.f));
    float a   = 1.0f / (sd + 1e-8f);
    g_ab[k]         = DT * a;
    g_ab[KCOLS + k] = DT * (-mu * a);
}

// -------- K6: ECF, Chebyshev recurrence with 2 packed chain sets (4 rows/iter) --------
__global__ void __launch_bounds__(256) k_ecf() {
    __shared__ float part[8][2 * NPTS][32];
    const int lane = threadIdx.x & 31;
    const int w    = threadIdx.x >> 5;
    const int k    = blockIdx.x * 32 + lane;
    const int b0   = blockIdx.y * 512 + w * 64;

    const float a = g_ab[k];
    const float b = g_ab[KCOLS + k];

    const ull ONE = dup2(1.0f);
    const ull NONE = dup2(-1.0f);
    const ull S1 = dup2(-1.6666667e-1f), S2 = dup2(8.3333333e-3f), S3 = dup2(-1.9841270e-4f);
    const ull C1 = dup2(-0.5f), C2 = dup2(4.1666668e-2f), C3 = dup2(-1.3888889e-3f), C4 = dup2(2.4801587e-5f);

    ull accR[NPTS], accI[NPTS];
#pragma unroll
    for (int j = 0; j < NPTS; j++) { accR[j] = 0ULL; accI[j] = 0ULL; }

    for (int r = 0; r < 16; r++) {
        float p0 = g_proj[(size_t)(b0 + r)      * KCOLS + k];
        float p1 = g_proj[(size_t)(b0 + r + 16) * KCOLS + k];
        float p2 = g_proj[(size_t)(b0 + r + 32) * KCOLS + k];
        float p3 = g_proj[(size_t)(b0 + r + 48) * KCOLS + k];
        ull xA  = pack2(fmaf(a, p0, b), fmaf(a, p1, b));
        ull xB  = pack2(fmaf(a, p2, b), fmaf(a, p3, b));
        ull x2A = mul2(xA, xA);
        ull x2B = mul2(xB, xB);
        ull psA = ffma2(x2A, S3, S2); psA = ffma2(x2A, psA, S1); psA = ffma2(x2A, psA, ONE);
        ull psB = ffma2(x2B, S3, S2); psB = ffma2(x2B, psB, S1); psB = ffma2(x2B, psB, ONE);
        ull s1A = mul2(xA, psA);
        ull s1B = mul2(xB, psB);
        ull pcA = ffma2(x2A, C4, C3); pcA = ffma2(x2A, pcA, C2); pcA = ffma2(x2A, pcA, C1);
        ull pcB = ffma2(x2B, C4, C3); pcB = ffma2(x2B, pcB, C2); pcB = ffma2(x2B, pcB, C1);
        ull c1A = ffma2(x2A, pcA, ONE);
        ull c1B = ffma2(x2B, pcB, ONE);

        ull twocA = add2(c1A, c1A), twocB = add2(c1B, c1B);
        ull cA = c1A, sA = s1A, cB = c1B, sB = s1B;
        ull ncpA = NONE, nspA = 0ULL, ncpB = NONE, nspB = 0ULL;
        accR[0] = add2(accR[0], add2(c1A, c1B));
        accI[0] = add2(accI[0], add2(s1A, s1B));
#pragma unroll
        for (int m = 2; m <= NPTS; m++) {
            ull cnA = ffma2(twocA, cA, ncpA);
            ull snA = ffma2(twocA, sA, nspA);
            ull cnB = ffma2(twocB, cB, ncpB);
            ull snB = ffma2(twocB, sB, nspB);
            accR[m - 1] = add2(accR[m - 1], add2(cnA, cnB));
            accI[m - 1] = add2(accI[m - 1], add2(snA, snB));
            ncpA = neg2(cA); nspA = neg2(sA);
            ncpB = neg2(cB); nspB = neg2(sB);
            cA = cnA; sA = snA; cB = cnB; sB = snB;
        }
    }
#pragma unroll
    for (int j = 0; j < NPTS; j++) {
        float2 fr = unpack2(accR[j]);
        float2 fi = unpack2(accI[j]);
        part[w][j][lane]        = fr.x + fr.y;
        part[w][NPTS + j][lane] = fi.x + fi.y;
    }
    __syncthreads();
    for (int e = threadIdx.x; e < 2 * NPTS * 32; e += 256) {
        int jj = e >> 5;
        int ln = e & 31;
        float s = 0.f;
#pragma unroll
        for (int ww = 0; ww < 8; ww++) s += part[ww][jj][ln];
        int kk = blockIdx.x * 32 + ln;
        if (jj < NPTS) atomicAdd(&g_ecfR[jj * KCOLS + kk], s);
        else           atomicAdd(&g_ecfI[(jj - NPTS) * KCOLS + kk], s);
    }
}

// -------- K7: final scalar --------
__global__ void k_final(float* __restrict__ out) {
    __shared__ float sd[KCOLS];
    int k = threadIdx.x;
    float acc = 0.f;
#pragma unroll
    for (int j = 0; j < NPTS; j++) {
        float t   = (float)(j + 1) * DT;
        float er  = g_ecfR[j * KCOLS + k] * (1.0f / (float)BROWS);
        float ei  = g_ecfI[j * KCOLS + k] * (1.0f / (float)BROWS);
        float tcf = expf(-0.5f * t * t);
        float wq  = (j == 0 || j == NPTS - 1) ? (DT * 0.5f) : DT;
        float d   = er - tcf;
        acc = fmaf(wq, fmaf(d, d, ei * ei), acc);
    }
    sd[k] = acc;
    __syncthreads();
    for (int s = 256; s > 0; s >>= 1) {
        if (k < s) sd[k] += sd[k + s];
        __syncthreads();
    }
    if (k == 0) out[0] = sd[0] * (1.0f / (float)KCOLS);
}

extern "C" void kernel_launch(void* const* d_in, const int* in_sizes, int n_in,
                              void* d_out, int out_size) {
    const float* emb = (const float*)d_in[0];   // (8192, 2048)
    const float* dir = (const float*)d_in[1];   // (2048, 512)
    float* out = (float*)d_out;

    cudaFuncSetAttribute(k_gemm, cudaFuncAttributeMaxDynamicSharedMemorySize, GEMM_SMEM);

    k_zero<<<(NPTS * KCOLS + 255) / 256, 256>>>();
    k_norm2<<<128, 256>>>(dir);
    k_prepB<<<dim3(KCOLS / 64, DDIM / 64), 256>>>(dir);
    k_prepA<<<(BROWS * DDIM) / (256 * 8), 256>>>(emb);
    k_gemm<<<dim3(KCOLS / BN, BROWS / BM), 256, GEMM_SMEM>>>();
    k_ab<<<2, 256>>>();
    k_ecf<<<dim3(KCOLS / 32, BROWS / 512), 256>>>();
    k_final<<<1, KCOLS>>>(out);
}

// round 8
// speedup vs baseline: 3.4635x; 1.0025x over previous
#include <cuda_runtime.h>
#include <cuda_bf16.h>
#include <cstdint>

#define BROWS 8192
#define DDIM  2048
#define KCOLS 512
#define NPTS  17
#define DT    (2.0f / 17.0f)

// ---- GEMM tiling ----
#define BM 128
#define BN 128
#define BK 32
#define KITER (DDIM / BK)          // 64
#define TSTRIDE 40                 // bf16 halves per smem row (32 data + 8 pad)
#define TILEB (128 * TSTRIDE * 2)  // 10240 bytes per tile
#define OAH 0
#define OBH (1 * TILEB)
#define STAGEB (2 * TILEB)         // 20480 bytes per stage
#define NSTAGE 3
#define GEMM_SMEM (NSTAGE * STAGEB)  // 61440

// ---- device scratch ----
__device__ float g_norm2[KCOLS];
__device__ __nv_bfloat16 g_A_hi[(size_t)BROWS * DDIM];
__device__ __nv_bfloat16 g_Bt_hi[KCOLS * DDIM];   // [n][k] normalized bf16
__device__ float g_proj[(size_t)BROWS * KCOLS];
__device__ float g_stat[2 * KCOLS];
__device__ float g_ab[2 * KCOLS];
__device__ float g_ecfR[NPTS * KCOLS];
__device__ float g_ecfI[NPTS * KCOLS];

// ---- helpers ----
__device__ __forceinline__ uint32_t smem_u32(const void* p) {
    uint32_t a;
    asm("{ .reg .u64 t; cvta.to.shared.u64 t, %1; cvt.u32.u64 %0, t; }" : "=r"(a) : "l"(p));
    return a;
}
__device__ __forceinline__ void cp16(uint32_t dst, const void* src) {
    asm volatile("cp.async.cg.shared.global [%0], [%1], 16;" :: "r"(dst), "l"(src));
}
#define CP_COMMIT() asm volatile("cp.async.commit_group;" ::: "memory")
#define CP_WAIT1()  asm volatile("cp.async.wait_group 1;" ::: "memory")

__device__ __forceinline__ void ldsm4(uint32_t* r, uint32_t addr) {
    asm volatile("ldmatrix.sync.aligned.m8n8.x4.shared.b16 {%0,%1,%2,%3}, [%4];"
                 : "=r"(r[0]), "=r"(r[1]), "=r"(r[2]), "=r"(r[3]) : "r"(addr));
}
__device__ __forceinline__ void mma16816(float* d, const uint32_t* a, const uint32_t* b) {
    asm volatile("mma.sync.aligned.m16n8k16.row.col.f32.bf16.bf16.f32 "
                 "{%0,%1,%2,%3}, {%4,%5,%6,%7}, {%8,%9}, {%0,%1,%2,%3};"
                 : "+f"(d[0]), "+f"(d[1]), "+f"(d[2]), "+f"(d[3])
                 : "r"(a[0]), "r"(a[1]), "r"(a[2]), "r"(a[3]), "r"(b[0]), "r"(b[1]));
}

typedef unsigned long long ull;
__device__ __forceinline__ ull ffma2(ull a, ull b, ull c) {
    ull d; asm("fma.rn.f32x2 %0, %1, %2, %3;" : "=l"(d) : "l"(a), "l"(b), "l"(c)); return d;
}
__device__ __forceinline__ ull mul2(ull a, ull b) {
    ull d; asm("mul.rn.f32x2 %0, %1, %2;" : "=l"(d) : "l"(a), "l"(b)); return d;
}
__device__ __forceinline__ ull add2(ull a, ull b) {
    ull d; asm("add.rn.f32x2 %0, %1, %2;" : "=l"(d) : "l"(a), "l"(b)); return d;
}
__device__ __forceinline__ ull dup2(float a) {
    ull r; asm("mov.b64 %0, {%1, %1};" : "=l"(r) : "f"(a)); return r;
}
__device__ __forceinline__ ull pack2(float lo, float hi) {
    ull r; asm("mov.b64 %0, {%1, %2};" : "=l"(r) : "f"(lo), "f"(hi)); return r;
}
__device__ __forceinline__ float2 unpack2(ull v) {
    float2 r; asm("mov.b64 {%0, %1}, %2;" : "=f"(r.x), "=f"(r.y) : "l"(v)); return r;
}
__device__ __forceinline__ ull neg2(ull v) { return v ^ 0x8000000080000000ULL; }

// -------- K0: zero accumulators --------
__global__ void k_zero() {
    int i = blockIdx.x * blockDim.x + threadIdx.x;
    if (i < KCOLS) g_norm2[i] = 0.f;
    if (i < 2 * KCOLS) g_stat[i] = 0.f;
    if (i < NPTS * KCOLS) { g_ecfR[i] = 0.f; g_ecfI[i] = 0.f; }
}

// -------- K1: column squared norms of directions --------
__global__ void k_norm2(const float* __restrict__ dir) {
    int k  = (blockIdx.x & 1) * 256 + threadIdx.x;
    int d0 = (blockIdx.x >> 1) * 32;
    float s = 0.f;
#pragma unroll 8
    for (int d = 0; d < 32; d++) {
        float v = dir[(size_t)(d0 + d) * KCOLS + k];
        s = fmaf(v, v, s);
    }
    atomicAdd(&g_norm2[k], s);
}

// -------- K2: normalize + transpose + bf16 round of directions --------
__global__ void __launch_bounds__(256) k_prepB(const float* __restrict__ dir) {
    __shared__ float s[64][65];
    int t = threadIdx.x;
    int n0t = blockIdx.x * 64;
    int d0  = blockIdx.y * 64;
#pragma unroll
    for (int jj = 0; jj < 4; jj++) {
        int flat = jj * 256 + t;
        int d = flat >> 4;
        int nq = flat & 15;
        float4 v = *(const float4*)(dir + (size_t)(d0 + d) * KCOLS + n0t + nq * 4);
        s[d][nq * 4 + 0] = v.x; s[d][nq * 4 + 1] = v.y;
        s[d][nq * 4 + 2] = v.z; s[d][nq * 4 + 3] = v.w;
    }
    __syncthreads();
#pragma unroll
    for (int jj = 0; jj < 4; jj++) {
        int flat = jj * 256 + t;
        int n = flat >> 4;
        int dq = flat & 15;
        float rn = rsqrtf(fmaxf(g_norm2[n0t + n], 1e-24f));
        float x0 = s[dq * 4 + 0][n] * rn, x1 = s[dq * 4 + 1][n] * rn;
        float x2 = s[dq * 4 + 2][n] * rn, x3 = s[dq * 4 + 3][n] * rn;
        __nv_bfloat162 h01 = __floats2bfloat162_rn(x0, x1);
        __nv_bfloat162 h23 = __floats2bfloat162_rn(x2, x3);
        size_t o = (size_t)(n0t + n) * DDIM + d0 + dq * 4;
        *(uint2*)(g_Bt_hi + o) = make_uint2(*(uint32_t*)&h01, *(uint32_t*)&h23);
    }
}

// -------- K3: round A to bf16 --------
__global__ void __launch_bounds__(256) k_prepA(const float* __restrict__ A) {
    size_t idx = ((size_t)blockIdx.x * 256 + threadIdx.x) * 8;
    float4 v0 = *(const float4*)(A + idx);
    float4 v1 = *(const float4*)(A + idx + 4);
    __nv_bfloat162 h01 = __floats2bfloat162_rn(v0.x, v0.y);
    __nv_bfloat162 h23 = __floats2bfloat162_rn(v0.z, v0.w);
    __nv_bfloat162 h45 = __floats2bfloat162_rn(v1.x, v1.y);
    __nv_bfloat162 h67 = __floats2bfloat162_rn(v1.z, v1.w);
    *(uint4*)(g_A_hi + idx) = make_uint4(*(uint32_t*)&h01, *(uint32_t*)&h23,
                                         *(uint32_t*)&h45, *(uint32_t*)&h67);
}

// -------- K4: HMMA bf16 GEMM (single product) with fused column stats --------
__global__ void __launch_bounds__(256, 2) k_gemm(void) {
    extern __shared__ char smem[];
    const uint32_t sbase = smem_u32(smem);
    const int tid  = threadIdx.x;
    const int lane = tid & 31;
    const int wid  = tid >> 5;
    const int wm   = wid >> 2;       // 0..1  (64-row strip)
    const int wn   = wid & 3;        // 0..3  (32-col strip)
    const int n0 = blockIdx.x * BN;
    const int m0 = blockIdx.y * BM;

    const int lrow = tid >> 1;
    const int lcb  = (tid & 1) * 32;
    const int lke  = (tid & 1) * 16;
    const size_t aoff = (size_t)(m0 + lrow) * DDIM + lke;
    const size_t boff = (size_t)(n0 + lrow) * DDIM + lke;
    const uint32_t ldst = lrow * (TSTRIDE * 2) + lcb;

#define ISSUE(stg, ks) do {                                                   \
    uint32_t _d = sbase + (stg) * STAGEB + ldst;                              \
    size_t _k = (size_t)(ks) * BK;                                            \
    cp16(_d + OAH,      g_A_hi  + aoff + _k);                                 \
    cp16(_d + OAH + 16, g_A_hi  + aoff + _k + 8);                             \
    cp16(_d + OBH,      g_Bt_hi + boff + _k);                                 \
    cp16(_d + OBH + 16, g_Bt_hi + boff + _k + 8);                             \
} while (0)

    float acc[4][4][4];
#pragma unroll
    for (int i = 0; i < 4; i++)
#pragma unroll
        for (int j = 0; j < 4; j++)
#pragma unroll
            for (int q = 0; q < 4; q++) acc[i][j][q] = 0.f;

    const uint32_t aRowB = (wm * 64 + (lane & 15)) * (TSTRIDE * 2) + ((lane >> 4) & 1) * 16;
    const uint32_t bRow4 = (wn * 32 + ((lane >> 4) & 1) * 8 + (lane & 7)) * (TSTRIDE * 2)
                         + ((lane >> 3) & 1) * 16;

    ISSUE(0, 0); CP_COMMIT();
    ISSUE(1, 1); CP_COMMIT();

    for (int i = 0; i < KITER; i++) {
        CP_WAIT1();
        __syncthreads();
        // prefetch into the third slot while computing this one
        if (i + 2 < KITER) {
            int slot = (i + 2) % NSTAGE;
            ISSUE(slot, i + 2);
        }
        CP_COMMIT();
        const uint32_t sb = sbase + (i % NSTAGE) * STAGEB;
#pragma unroll
        for (int k16 = 0; k16 < 2; k16++) {
            const uint32_t kb = k16 * 32;
            uint32_t af[4][4], bh[4][2];
#pragma unroll
            for (int mf = 0; mf < 4; mf++)
                ldsm4(af[mf], sb + OAH + aRowB + mf * 16 * (TSTRIDE * 2) + kb);
#pragma unroll
            for (int p = 0; p < 2; p++) {
                uint32_t tmp[4];
                ldsm4(tmp, sb + OBH + bRow4 + p * 16 * (TSTRIDE * 2) + kb);
                bh[2 * p][0] = tmp[0]; bh[2 * p][1] = tmp[1];
                bh[2 * p + 1][0] = tmp[2]; bh[2 * p + 1][1] = tmp[3];
            }
#pragma unroll
            for (int mf = 0; mf < 4; mf++)
#pragma unroll
                for (int nf = 0; nf < 4; nf++)
                    mma16816(acc[mf][nf], af[mf], bh[nf]);
        }
    }

    // ---- epilogue: store proj + fused column stats ----
    float sc[8], sq[8];
#pragma unroll
    for (int e = 0; e < 8; e++) { sc[e] = 0.f; sq[e] = 0.f; }

#pragma unroll
    for (int mf = 0; mf < 4; mf++) {
        const int m = m0 + wm * 64 + mf * 16 + (lane >> 2);
#pragma unroll
        for (int nf = 0; nf < 4; nf++) {
            const int n = n0 + wn * 32 + nf * 8 + (lane & 3) * 2;
            float* c = acc[mf][nf];
            *(float2*)&g_proj[(size_t)m * KCOLS + n]       = make_float2(c[0], c[1]);
            *(float2*)&g_proj[(size_t)(m + 8) * KCOLS + n] = make_float2(c[2], c[3]);
            sc[nf * 2 + 0] += c[0] + c[2];
            sc[nf * 2 + 1] += c[1] + c[3];
            sq[nf * 2 + 0] += c[0] * c[0] + c[2] * c[2];
            sq[nf * 2 + 1] += c[1] * c[1] + c[3] * c[3];
        }
    }
#pragma unroll
    for (int off = 16; off >= 4; off >>= 1)
#pragma unroll
        for (int e = 0; e < 8; e++) {
            sc[e] += __shfl_down_sync(0xFFFFFFFF, sc[e], off);
            sq[e] += __shfl_down_sync(0xFFFFFFFF, sq[e], off);
        }
    if (lane < 4) {
#pragma unroll
        for (int nf = 0; nf < 4; nf++)
#pragma unroll
            for (int p = 0; p < 2; p++) {
                int col = n0 + wn * 32 + nf * 8 + 2 * lane + p;
                atomicAdd(&g_stat[col],         sc[nf * 2 + p]);
                atomicAdd(&g_stat[KCOLS + col], sq[nf * 2 + p]);
            }
    }
}

// -------- K5: a,b affine --------
__global__ void k_ab() {
    int k = blockIdx.x * blockDim.x + threadIdx.x;
    if (k >= KCOLS) return;
    float sum = g_stat[k];
    float sq  = g_stat[KCOLS + k];
    float mu  = sum * (1.0f / (float)BROWS);
    float var = (sq - (float)BROWS * mu * mu) * (1.0f / (float)(BROWS - 1));
    float sd  = sqrtf(fmaxf(var, 0.f));
    float a   = 1.0f / (sd + 1e-8f);
    g_ab[k]         = DT * a;
    g_ab[KCOLS + k] = DT * (-mu * a);
}

// -------- K6: ECF, Chebyshev recurrence with 2 packed chain sets (4 rows/iter) --------
__global__ void __launch_bounds__(256) k_ecf() {
    __shared__ float part[8][2 * NPTS][32];
    const int lane = threadIdx.x & 31;
    const int w    = threadIdx.x >> 5;
    const int k    = blockIdx.x * 32 + lane;
    const int b0   = blockIdx.y * 512 + w * 64;

    const float a = g_ab[k];
    const float b = g_ab[KCOLS + k];

    const ull ONE = dup2(1.0f);
    const ull NONE = dup2(-1.0f);
    const ull S1 = dup2(-1.6666667e-1f), S2 = dup2(8.3333333e-3f), S3 = dup2(-1.9841270e-4f);
    const ull C1 = dup2(-0.5f), C2 = dup2(4.1666668e-2f), C3 = dup2(-1.3888889e-3f), C4 = dup2(2.4801587e-5f);

    ull accR[NPTS], accI[NPTS];
#pragma unroll
    for (int j = 0; j < NPTS; j++) { accR[j] = 0ULL; accI[j] = 0ULL; }

    for (int r = 0; r < 16; r++) {
        float p0 = g_proj[(size_t)(b0 + r)      * KCOLS + k];
        float p1 = g_proj[(size_t)(b0 + r + 16) * KCOLS + k];
        float p2 = g_proj[(size_t)(b0 + r + 32) * KCOLS + k];
        float p3 = g_proj[(size_t)(b0 + r + 48) * KCOLS + k];
        ull xA  = pack2(fmaf(a, p0, b), fmaf(a, p1, b));
        ull xB  = pack2(fmaf(a, p2, b), fmaf(a, p3, b));
        ull x2A = mul2(xA, xA);
        ull x2B = mul2(xB, xB);
        ull psA = ffma2(x2A, S3, S2); psA = ffma2(x2A, psA, S1); psA = ffma2(x2A, psA, ONE);
        ull psB = ffma2(x2B, S3, S2); psB = ffma2(x2B, psB, S1); psB = ffma2(x2B, psB, ONE);
        ull s1A = mul2(xA, psA);
        ull s1B = mul2(xB, psB);
        ull pcA = ffma2(x2A, C4, C3); pcA = ffma2(x2A, pcA, C2); pcA = ffma2(x2A, pcA, C1);
        ull pcB = ffma2(x2B, C4, C3); pcB = ffma2(x2B, pcB, C2); pcB = ffma2(x2B, pcB, C1);
        ull c1A = ffma2(x2A, pcA, ONE);
        ull c1B = ffma2(x2B, pcB, ONE);

        ull twocA = add2(c1A, c1A), twocB = add2(c1B, c1B);
        ull cA = c1A, sA = s1A, cB = c1B, sB = s1B;
        ull ncpA = NONE, nspA = 0ULL, ncpB = NONE, nspB = 0ULL;
        accR[0] = add2(accR[0], add2(c1A, c1B));
        accI[0] = add2(accI[0], add2(s1A, s1B));
#pragma unroll
        for (int m = 2; m <= NPTS; m++) {
            ull cnA = ffma2(twocA, cA, ncpA);
            ull snA = ffma2(twocA, sA, nspA);
            ull cnB = ffma2(twocB, cB, ncpB);
            ull snB = ffma2(twocB, sB, nspB);
            accR[m - 1] = add2(accR[m - 1], add2(cnA, cnB));
            accI[m - 1] = add2(accI[m - 1], add2(snA, snB));
            ncpA = neg2(cA); nspA = neg2(sA);
            ncpB = neg2(cB); nspB = neg2(sB);
            cA = cnA; sA = snA; cB = cnB; sB = snB;
        }
    }
#pragma unroll
    for (int j = 0; j < NPTS; j++) {
        float2 fr = unpack2(accR[j]);
        float2 fi = unpack2(accI[j]);
        part[w][j][lane]        = fr.x + fr.y;
        part[w][NPTS + j][lane] = fi.x + fi.y;
    }
    __syncthreads();
    for (int e = threadIdx.x; e < 2 * NPTS * 32; e += 256) {
        int jj = e >> 5;
        int ln = e & 31;
        float s = 0.f;
#pragma unroll
        for (int ww = 0; ww < 8; ww++) s += part[ww][jj][ln];
        int kk = blockIdx.x * 32 + ln;
        if (jj < NPTS) atomicAdd(&g_ecfR[jj * KCOLS + kk], s);
        else           atomicAdd(&g_ecfI[(jj - NPTS) * KCOLS + kk], s);
    }
}

// -------- K7: final scalar --------
__global__ void k_final(float* __restrict__ out) {
    __shared__ float sd[KCOLS];
    int k = threadIdx.x;
    float acc = 0.f;
#pragma unroll
    for (int j = 0; j < NPTS; j++) {
        float t   = (float)(j + 1) * DT;
        float er  = g_ecfR[j * KCOLS + k] * (1.0f / (float)BROWS);
        float ei  = g_ecfI[j * KCOLS + k] * (1.0f / (float)BROWS);
        float tcf = expf(-0.5f * t * t);
        float wq  = (j == 0 || j == NPTS - 1) ? (DT * 0.5f) : DT;
        float d   = er - tcf;
        acc = fmaf(wq, fmaf(d, d, ei * ei), acc);
    }
    sd[k] = acc;
    __syncthreads();
    for (int s = 256; s > 0; s >>= 1) {
        if (k < s) sd[k] += sd[k + s];
        __syncthreads();
    }
    if (k == 0) out[0] = sd[0] * (1.0f / (float)KCOLS);
}

extern "C" void kernel_launch(void* const* d_in, const int* in_sizes, int n_in,
                              void* d_out, int out_size) {
    const float* emb = (const float*)d_in[0];   // (8192, 2048)
    const float* dir = (const float*)d_in[1];   // (2048, 512)
    float* out = (float*)d_out;

    cudaFuncSetAttribute(k_gemm, cudaFuncAttributeMaxDynamicSharedMemorySize, GEMM_SMEM);

    k_zero<<<(NPTS * KCOLS + 255) / 256, 256>>>();
    k_norm2<<<128, 256>>>(dir);
    k_prepB<<<dim3(KCOLS / 64, DDIM / 64), 256>>>(dir);
    k_prepA<<<(BROWS * DDIM) / (256 * 8), 256>>>(emb);
    k_gemm<<<dim3(KCOLS / BN, BROWS / BM), 256, GEMM_SMEM>>>();
    k_ab<<<2, 256>>>();
    k_ecf<<<dim3(KCOLS / 32, BROWS / 512), 256>>>();
    k_final<<<1, KCOLS>>>(out);
}